// round 11
// baseline (speedup 1.0000x reference)
#include <cuda_runtime.h>
#include <cuda_fp16.h>
#include <cstdint>

#define HW     576
#define CIN    512
#define HD     64
#define NTOK   2304      // V_NUM * HW
#define NPAIR  16        // groups(2) * heads(8)
#define NB     8
#define QSCALE (0.125f * 1.4426950408889634f)   // hd^-0.5 * log2(e)

// Scratch (device globals: allocation-free rule). All fp16.
__device__ __align__(16) __half g_xt[NB * HW * CIN];     // x transposed [b][hw][c]
__device__ __align__(16) __half g_wq[3 * CIN * CIN];     // w_qkv [o][c]
__device__ __align__(16) __half g_wp[CIN * CIN];         // w_proj [o][c]
__device__ __align__(16) __half g_q[NPAIR * NTOK * HD];  // [p][n][d], scale folded
__device__ __align__(16) __half g_k[NPAIR * NTOK * HD];  // [p][n][d]
__device__ __align__(16) __half g_v[NPAIR * HD * NTOK];  // [p][d][n]
__device__ __align__(16) __half g_ao[NB * HW * CIN];     // attn out [b][hw][c]

// ---------------- helpers ----------------
__device__ __forceinline__ void mma16(float* c, const uint32_t* a, uint32_t b0, uint32_t b1) {
    asm("mma.sync.aligned.m16n8k16.row.col.f32.f16.f16.f32 "
        "{%0,%1,%2,%3}, {%4,%5,%6,%7}, {%8,%9}, {%0,%1,%2,%3};\n"
        : "+f"(c[0]), "+f"(c[1]), "+f"(c[2]), "+f"(c[3])
        : "r"(a[0]), "r"(a[1]), "r"(a[2]), "r"(a[3]), "r"(b0), "r"(b1));
}
// fp16 accumulate variant: D/C are 2 x .f16x2 regs (half2 row r, half2 row r+8)
__device__ __forceinline__ void mma16h(uint32_t* c, const uint32_t* a, uint32_t b0, uint32_t b1) {
    asm("mma.sync.aligned.m16n8k16.row.col.f16.f16.f16.f16 "
        "{%0,%1}, {%2,%3,%4,%5}, {%6,%7}, {%0,%1};\n"
        : "+r"(c[0]), "+r"(c[1])
        : "r"(a[0]), "r"(a[1]), "r"(a[2]), "r"(a[3]), "r"(b0), "r"(b1));
}
__device__ __forceinline__ void ldsm4(uint32_t* d, uint32_t a) {
    asm volatile("ldmatrix.sync.aligned.m8n8.x4.shared.b16 {%0,%1,%2,%3}, [%4];\n"
        : "=r"(d[0]), "=r"(d[1]), "=r"(d[2]), "=r"(d[3]) : "r"(a));
}
__device__ __forceinline__ uint32_t s2u(const void* p) {
    return (uint32_t)__cvta_generic_to_shared(p);
}
__device__ __forceinline__ void cpa16(uint32_t dst, const void* src) {
    asm volatile("cp.async.cg.shared.global [%0], [%1], 16;\n" :: "r"(dst), "l"(src));
}
__device__ __forceinline__ void cpcommit() {
    asm volatile("cp.async.commit_group;\n" ::: "memory");
}
#define CPWAIT(n) asm volatile("cp.async.wait_group %0;\n" :: "n"(n) : "memory")

// fp16 LDSM lane offsets (bytes). strideB = row stride in bytes.
__device__ __forceinline__ uint32_t a_off16(int lane, int strideB) {
    return (uint32_t)(((lane & 7) + ((lane >> 3) & 1) * 8) * strideB + (lane >> 4) * 16);
}
__device__ __forceinline__ uint32_t b_off16(int lane, int strideB) {
    return (uint32_t)(((lane & 7) + ((lane >> 4) & 1) * 8) * strideB + ((lane >> 3) & 1) * 16);
}

#define STRB 144      // 72 halves per smem row
#define H2(u) (*(__half2*)&(u))

// ---------------------------------------------------------------------------
// Fused prologue: blocks [0,1024) convert weights; blocks [1024,1600)
// transpose+convert x [b][c][hw] -> g_xt [b][hw][c] fp16 (64x64 tiles).
// ---------------------------------------------------------------------------
__global__ __launch_bounds__(256) void prep(const float4* __restrict__ wq,
                                            const float4* __restrict__ wp,
                                            const float* __restrict__ x) {
    __shared__ float sT[64 * 65];
    const int tid = threadIdx.x;
    if (blockIdx.x < 1024) {
        int i = blockIdx.x * 256 + tid;
        float4 v; __half* dst;
        if (i < 196608) { v = wq[i];          dst = g_wq + i * 4; }
        else            { v = wp[i - 196608]; dst = g_wp + (i - 196608) * 4; }
        *(__half2*)dst       = __floats2half2_rn(v.x, v.y);
        *(__half2*)(dst + 2) = __floats2half2_rn(v.z, v.w);
        return;
    }
    const int bid = blockIdx.x - 1024;               // 576 tiles: 9 x 8 x 8
    const int hw0 = (bid % 9) * 64;
    const int c0  = ((bid / 9) & 7) * 64;
    const int b   = bid / 72;
#pragma unroll
    for (int rr = 0; rr < 4; rr++) {
        int f = tid + rr * 256, row = f >> 4, h4 = (f & 15) * 4;
        float4 v = *(const float4*)&x[((b * CIN) + c0 + row) * HW + hw0 + h4];
        sT[row * 65 + h4 + 0] = v.x; sT[row * 65 + h4 + 1] = v.y;
        sT[row * 65 + h4 + 2] = v.z; sT[row * 65 + h4 + 3] = v.w;
    }
    __syncthreads();
    {
        int f = tid, hwr = f >> 2, cc = (f & 3) * 16;   // 256 items exactly
        __half* dst = g_xt + ((b * HW) + hw0 + hwr) * CIN + c0 + cc;
#pragma unroll
        for (int j = 0; j < 8; j++)
            *(__half2*)(dst + 2 * j) =
                __floats2half2_rn(sT[(cc + 2 * j) * 65 + hwr], sT[(cc + 2 * j + 1) * 65 + hwr]);
    }
}

// ---------------------------------------------------------------------------
// Kernel A: QKV. D[m=hw 64][n=o 128] = X[hw][c] @ W[o][c]^T, K=512, BK=64.
// ---------------------------------------------------------------------------
__global__ __launch_bounds__(256, 3) void qkv_mma() {
    extern __shared__ __half smh[];
    const uint32_t sXb = s2u(smh);
    const uint32_t sWb = sXb + 2 * 4608 * 2;
    const int tid = threadIdx.x, wp = tid >> 5, lane = tid & 31;
    const int r = lane >> 2, q = lane & 3;
    const int wm = wp >> 2, wn = wp & 3;
    const int hw0 = blockIdx.x * 64, o0 = blockIdx.y * 128, b = blockIdx.z;
    const uint32_t aof = a_off16(lane, STRB), bof = b_off16(lane, STRB);

#define QKV_PF(K0, BUF) {                                                       \
    _Pragma("unroll") for (int rr = 0; rr < 2; rr++) {                          \
        int f = tid + rr * 256, row = f >> 3, ch = (f & 7) * 8;                 \
        cpa16(sXb + (uint32_t)((BUF) * 4608 + row * 72 + ch) * 2u,              \
              g_xt + ((b * HW) + hw0 + row) * CIN + (K0) + ch);                 \
    }                                                                           \
    _Pragma("unroll") for (int rr = 0; rr < 4; rr++) {                          \
        int f = tid + rr * 256, row = f >> 3, ch = (f & 7) * 8;                 \
        cpa16(sWb + (uint32_t)((BUF) * 9216 + row * 72 + ch) * 2u,              \
              g_wq + (o0 + row) * CIN + (K0) + ch);                             \
    }                                                                           \
    cpcommit(); }

    QKV_PF(0, 0);
    float acc[2][4][4] = {};

    for (int kk = 0; kk < 8; kk++) {
        const int buf = kk & 1;
        CPWAIT(0);
        __syncthreads();
        if (kk + 1 < 8) QKV_PF((kk + 1) * 64, buf ^ 1);

        const uint32_t xa = sXb + (uint32_t)(buf * 4608 + wm * 32 * 72) * 2u + aof;
        const uint32_t wa = sWb + (uint32_t)(buf * 9216 + wn * 32 * 72) * 2u + bof;
#pragma unroll
        for (int s = 0; s < 4; s++) {
            uint32_t aX[2][4];
            ldsm4(aX[0], xa + s * 32);
            ldsm4(aX[1], xa + 16 * STRB + s * 32);
#pragma unroll
            for (int j2 = 0; j2 < 2; j2++) {
                uint32_t bb[4]; ldsm4(bb, wa + j2 * 16 * STRB + s * 32);
#pragma unroll
                for (int mi = 0; mi < 2; mi++) {
                    mma16(acc[mi][j2 * 2],     aX[mi], bb[0], bb[1]);
                    mma16(acc[mi][j2 * 2 + 1], aX[mi], bb[2], bb[3]);
                }
            }
        }
    }

    const int g2 = b >> 2, vv = b & 3;
#pragma unroll
    for (int mi = 0; mi < 2; mi++) {
        int hwr = hw0 + wm * 32 + mi * 16 + r;
        int n0t = vv * HW + hwr, n1t = n0t + 8;
#pragma unroll
        for (int nj = 0; nj < 4; nj++) {
            int o = o0 + wn * 32 + nj * 8 + 2 * q;
            int head = o / 192, rem = o - head * 192, which = rem >> 6, d = rem & 63;
            int pp = g2 * 8 + head;
            float c0 = acc[mi][nj][0], c1 = acc[mi][nj][1];
            float c2 = acc[mi][nj][2], c3 = acc[mi][nj][3];
            if (which == 0) {
                *(__half2*)&g_q[(pp * NTOK + n0t) * HD + d] = __floats2half2_rn(c0 * QSCALE, c1 * QSCALE);
                *(__half2*)&g_q[(pp * NTOK + n1t) * HD + d] = __floats2half2_rn(c2 * QSCALE, c3 * QSCALE);
            } else if (which == 1) {
                *(__half2*)&g_k[(pp * NTOK + n0t) * HD + d] = __floats2half2_rn(c0, c1);
                *(__half2*)&g_k[(pp * NTOK + n1t) * HD + d] = __floats2half2_rn(c2, c3);
            } else {
                g_v[(pp * HD + d) * NTOK + n0t]     = __float2half_rn(c0);
                g_v[(pp * HD + d + 1) * NTOK + n0t] = __float2half_rn(c1);
                g_v[(pp * HD + d) * NTOK + n1t]     = __float2half_rn(c2);
                g_v[(pp * HD + d + 1) * NTOK + n1t] = __float2half_rn(c3);
            }
        }
    }
}

// ---------------------------------------------------------------------------
// Kernel B: flash attention fp16, round-8 shape (BM=128, 4 warps x m32,
// 3-stage ring) + softmax skew (S(h1) hides exp(h0)->PV(h0) chain) +
// row sums on FMA pipe (shuffle-reduce hoisted to epilogue).
// grid (18, 16), 128 thr.
// ---------------------------------------------------------------------------
__global__ __launch_bounds__(128, 2) void flash_mma() {
    extern __shared__ __half smh[];
    const uint32_t sQb = s2u(smh);
    const uint32_t sKb = sQb + 128 * 72 * 2;
    const uint32_t sVb = sKb + 3 * 4608 * 2;

    const int tid = threadIdx.x, wm = tid >> 5, lane = tid & 31;
    const int r = lane >> 2, q = lane & 3;
    const int p = blockIdx.y, m0 = blockIdx.x * 128;

    const __half* Qb = g_q + (p * NTOK + m0) * HD;
    const __half* Kb = g_k + p * NTOK * HD;
    const __half* Vb = g_v + p * HD * NTOK;

    const uint32_t aof = a_off16(lane, STRB), bof = b_off16(lane, STRB);

#define FL_PF(N0, BUF) {                                                        \
    _Pragma("unroll") for (int rr = 0; rr < 4; rr++) {                          \
        int f = tid + rr * 128, row = f >> 3, ch = (f & 7) * 8;                 \
        cpa16(sKb + (uint32_t)((BUF) * 4608 + row * 72 + ch) * 2u,              \
              Kb + ((N0) + row) * HD + ch);                                     \
        cpa16(sVb + (uint32_t)((BUF) * 4608 + row * 72 + ch) * 2u,              \
              Vb + row * NTOK + (N0) + ch);                                     \
    }                                                                           \
    cpcommit(); }

    // stage Q (128 rows x 64 halves), then first two K/V stages
#pragma unroll
    for (int rr = 0; rr < 8; rr++) {
        int f = tid + rr * 128, row = f >> 3, ch = (f & 7) * 8;
        cpa16(sQb + (uint32_t)(row * 72 + ch) * 2u, Qb + row * HD + ch);
    }
    cpcommit();
    FL_PF(0, 0);
    FL_PF(64, 1);

    CPWAIT(1);            // Q + stage0 ready
    __syncthreads();
    uint32_t qf[2][4][4];
#pragma unroll
    for (int st = 0; st < 2; st++) {
        const uint32_t qa = sQb + (uint32_t)((wm * 32 + st * 16) * 72) * 2u + aof;
#pragma unroll
        for (int s = 0; s < 4; s++) ldsm4(qf[st][s], qa + s * 32);
    }

    float rO[2][8][4] = {};     // [strip][d-tile][4]
    float sr[2] = {0.f, 0.f};   // per-thread partial row sums (row r)
    float sr8[2] = {0.f, 0.f};  // (row r+8)

// S(m32 x n32) for half H into ShD; fp16 accumulate
#define S_HALF(H, ShD) {                                                         \
    _Pragma("unroll") for (int s = 0; s < 4; s++)                                \
        _Pragma("unroll") for (int jn = 0; jn < 2; jn++) {                       \
            uint32_t bb[4];                                                      \
            ldsm4(bb, ka + (uint32_t)(((H) * 32 + jn * 16) * STRB) + s * 32);    \
            _Pragma("unroll") for (int st = 0; st < 2; st++) {                   \
                mma16h(ShD[st][jn * 2],     qf[st][s], bb[0], bb[1]);            \
                mma16h(ShD[st][jn * 2 + 1], qf[st][s], bb[2], bb[3]);            \
            }                                                                    \
        } }

// exp2 + pack + FMA-pipe row-sum accumulation
#define EXP_HALF(ShD, pfD) {                                                     \
    _Pragma("unroll") for (int st = 0; st < 2; st++) {                           \
        _Pragma("unroll") for (int t = 0; t < 2; t++) {                          \
            __half2 e0 = h2exp2(H2(ShD[st][2 * t][0]));                          \
            __half2 e1 = h2exp2(H2(ShD[st][2 * t][1]));                          \
            __half2 e2 = h2exp2(H2(ShD[st][2 * t + 1][0]));                      \
            __half2 e3 = h2exp2(H2(ShD[st][2 * t + 1][1]));                      \
            pfD[st][t][0] = *(uint32_t*)&e0;                                     \
            pfD[st][t][1] = *(uint32_t*)&e1;                                     \
            pfD[st][t][2] = *(uint32_t*)&e2;                                     \
            pfD[st][t][3] = *(uint32_t*)&e3;                                     \
        }                                                                        \
        __half2 a0 = __hadd2(H2(pfD[st][0][0]), H2(pfD[st][1][0]));              \
        __half2 a1 = __hadd2(H2(pfD[st][0][2]), H2(pfD[st][1][2]));              \
        __half2 b0 = __hadd2(H2(pfD[st][0][1]), H2(pfD[st][1][1]));              \
        __half2 b1 = __hadd2(H2(pfD[st][0][3]), H2(pfD[st][1][3]));              \
        float2 fa0 = __half22float2(a0), fa1 = __half22float2(a1);               \
        float2 fb0 = __half22float2(b0), fb1 = __half22float2(b1);               \
        sr[st]  += (fa0.x + fa0.y) + (fa1.x + fa1.y);                            \
        sr8[st] += (fb0.x + fb0.y) + (fb1.x + fb1.y);                            \
    } }

// O(m32 x d64) += P(half H) @ V
#define PV_HALF(H, pfD) {                                                        \
    _Pragma("unroll") for (int t = 0; t < 2; t++)                                \
        _Pragma("unroll") for (int j = 0; j < 4; j++) {                          \
            uint32_t bb[4];                                                      \
            ldsm4(bb, va + (uint32_t)(j * 16 * STRB) + ((H) * 32 + t * 16) * 2); \
            _Pragma("unroll") for (int st = 0; st < 2; st++) {                   \
                mma16(rO[st][2 * j],     pfD[st][t], bb[0], bb[1]);              \
                mma16(rO[st][2 * j + 1], pfD[st][t], bb[2], bb[3]);              \
            }                                                                    \
        } }

    for (int it = 0; it < 36; it++) {
        const int buf = it % 3;
        if (it) { CPWAIT(1); __syncthreads(); }
        if (it + 2 < 36) FL_PF((it + 2) * 64, (it + 2) % 3);

        const uint32_t ka = sKb + (uint32_t)(buf * 4608) * 2u + bof;
        const uint32_t va = sVb + (uint32_t)(buf * 4608) * 2u + bof;

        // skewed schedule: S0, exp0, S1, PV0, exp1, PV1
        uint32_t Sh0[2][4][2] = {};
        S_HALF(0, Sh0);
        uint32_t pf0[2][2][4];
        EXP_HALF(Sh0, pf0);
        uint32_t Sh1[2][4][2] = {};
        S_HALF(1, Sh1);
        PV_HALF(0, pf0);
        uint32_t pf1[2][2][4];
        EXP_HALF(Sh1, pf1);
        PV_HALF(1, pf1);
    }

    // epilogue: quad shuffle-reduce of row sums, normalize, write g_ao
    const int head = p & 7, gi = p >> 3;
#pragma unroll
    for (int st = 0; st < 2; st++) {
        float l0 = sr[st], l1 = sr8[st];
        l0 += __shfl_xor_sync(0xffffffffu, l0, 1);
        l0 += __shfl_xor_sync(0xffffffffu, l0, 2);
        l1 += __shfl_xor_sync(0xffffffffu, l1, 1);
        l1 += __shfl_xor_sync(0xffffffffu, l1, 2);
        const float i0 = 1.f / l0, i1 = 1.f / l1;
        const int row0 = m0 + wm * 32 + st * 16 + r, row1 = row0 + 8;
        const int v0 = row0 / HW, v1 = row1 / HW;
        __half* o0p = g_ao + ((gi * 4 + v0) * HW + (row0 - v0 * HW)) * CIN + head * 64;
        __half* o1p = g_ao + ((gi * 4 + v1) * HW + (row1 - v1 * HW)) * CIN + head * 64;
#pragma unroll
        for (int dt = 0; dt < 8; dt++) {
            *(__half2*)&o0p[dt * 8 + 2 * q] =
                __floats2half2_rn(rO[st][dt][0] * i0, rO[st][dt][1] * i0);
            *(__half2*)&o1p[dt * 8 + 2 * q] =
                __floats2half2_rn(rO[st][dt][2] * i1, rO[st][dt][3] * i1);
        }
    }
}

// ---------------------------------------------------------------------------
// Kernel C: proj + bias. D[m=o 128][n=hw 64] = W[o][c] @ AO[hw][c]^T.
// ---------------------------------------------------------------------------
__global__ __launch_bounds__(256, 3) void proj_mma(const float* __restrict__ bias,
                                                   float* __restrict__ out) {
    extern __shared__ __half smh[];
    const uint32_t sWb = s2u(smh);
    const uint32_t sBb = sWb + 2 * 9216 * 2;
    const int tid = threadIdx.x, wp = tid >> 5, lane = tid & 31;
    const int r = lane >> 2, q = lane & 3;
    const int wm = wp >> 1, wn = wp & 1;
    const int o0 = blockIdx.x * 128, hw0 = blockIdx.y * 64, b = blockIdx.z;
    const uint32_t aof = a_off16(lane, STRB), bof = b_off16(lane, STRB);

#define PRJ_PF(K0, BUF) {                                                       \
    _Pragma("unroll") for (int rr = 0; rr < 4; rr++) {                          \
        int f = tid + rr * 256, row = f >> 3, ch = (f & 7) * 8;                 \
        cpa16(sWb + (uint32_t)((BUF) * 9216 + row * 72 + ch) * 2u,              \
              g_wp + (o0 + row) * CIN + (K0) + ch);                             \
    }                                                                           \
    _Pragma("unroll") for (int rr = 0; rr < 2; rr++) {                          \
        int f = tid + rr * 256, row = f >> 3, ch = (f & 7) * 8;                 \
        cpa16(sBb + (uint32_t)((BUF) * 4608 + row * 72 + ch) * 2u,              \
              g_ao + ((b * HW) + hw0 + row) * CIN + (K0) + ch);                 \
    }                                                                           \
    cpcommit(); }

    PRJ_PF(0, 0);
    float acc[2][4][4] = {};

    for (int kk = 0; kk < 8; kk++) {
        const int buf = kk & 1;
        CPWAIT(0);
        __syncthreads();
        if (kk + 1 < 8) PRJ_PF((kk + 1) * 64, buf ^ 1);

        const uint32_t wa = sWb + (uint32_t)(buf * 9216 + wm * 32 * 72) * 2u + aof;
        const uint32_t xa = sBb + (uint32_t)(buf * 4608 + wn * 32 * 72) * 2u + bof;
#pragma unroll
        for (int s = 0; s < 4; s++) {
            uint32_t aW[2][4];
            ldsm4(aW[0], wa + s * 32);
            ldsm4(aW[1], wa + 16 * STRB + s * 32);
#pragma unroll
            for (int j2 = 0; j2 < 2; j2++) {
                uint32_t bb[4]; ldsm4(bb, xa + j2 * 16 * STRB + s * 32);
#pragma unroll
                for (int mi = 0; mi < 2; mi++) {
                    mma16(acc[mi][j2 * 2],     aW[mi], bb[0], bb[1]);
                    mma16(acc[mi][j2 * 2 + 1], aW[mi], bb[2], bb[3]);
                }
            }
        }
    }

#pragma unroll
    for (int mi = 0; mi < 2; mi++) {
        int o_r = o0 + wm * 32 + mi * 16 + r;
        float bv0 = bias[o_r], bv1 = bias[o_r + 8];
#pragma unroll
        for (int nj = 0; nj < 4; nj++) {
            int hw = hw0 + wn * 32 + nj * 8 + 2 * q;
            *(float2*)&out[(b * CIN + o_r) * HW + hw] =
                make_float2(acc[mi][nj][0] + bv0, acc[mi][nj][1] + bv0);
            *(float2*)&out[(b * CIN + o_r + 8) * HW + hw] =
                make_float2(acc[mi][nj][2] + bv1, acc[mi][nj][3] + bv1);
        }
    }
}

// ---------------------------------------------------------------------------
extern "C" void kernel_launch(void* const* d_in, const int* in_sizes, int n_in,
                              void* d_out, int out_size) {
    const float* x      = (const float*)d_in[0];
    const float* w_qkv  = (const float*)d_in[1];
    const float* w_proj = (const float*)d_in[2];
    const float* b_proj = (const float*)d_in[3];
    float* out = (float*)d_out;

    cudaFuncSetAttribute(qkv_mma,   cudaFuncAttributeMaxDynamicSharedMemorySize, 55296);
    cudaFuncSetAttribute(flash_mma, cudaFuncAttributeMaxDynamicSharedMemorySize, 73728);
    cudaFuncSetAttribute(proj_mma,  cudaFuncAttributeMaxDynamicSharedMemorySize, 55296);

    prep<<<1600, 256>>>((const float4*)w_qkv, (const float4*)w_proj, x);
    qkv_mma<<<dim3(9, 12, 8), 256, 55296>>>();
    flash_mma<<<dim3(18, 16), 128, 73728>>>();
    proj_mma<<<dim3(4, 9, 8), 256, 55296>>>(b_proj, out);
}

// round 12
// speedup vs baseline: 1.5188x; 1.5188x over previous
#include <cuda_runtime.h>
#include <cuda_fp16.h>
#include <cstdint>

#define HW     576
#define CIN    512
#define HD     64
#define NTOK   2304      // V_NUM * HW
#define NPAIR  16        // groups(2) * heads(8)
#define NB     8
#define QSCALE (0.125f * 1.4426950408889634f)   // hd^-0.5 * log2(e)
#define ONES   0x3C003C00u                       // half2(1.0, 1.0)

// Scratch (device globals: allocation-free rule). All fp16.
__device__ __align__(16) __half g_xt[NB * HW * CIN];     // x transposed [b][hw][c]
__device__ __align__(16) __half g_wq[3 * CIN * CIN];     // w_qkv [o][c]
__device__ __align__(16) __half g_wp[CIN * CIN];         // w_proj [o][c]
__device__ __align__(16) __half g_q[NPAIR * NTOK * HD];  // [p][n][d], scale folded
__device__ __align__(16) __half g_k[NPAIR * NTOK * HD];  // [p][n][d]
__device__ __align__(16) __half g_v[NPAIR * HD * NTOK];  // [p][d][n]
__device__ __align__(16) __half g_ao[NB * HW * CIN];     // attn out [b][hw][c]

// ---------------- helpers ----------------
__device__ __forceinline__ void mma16(float* c, const uint32_t* a, uint32_t b0, uint32_t b1) {
    asm("mma.sync.aligned.m16n8k16.row.col.f32.f16.f16.f32 "
        "{%0,%1,%2,%3}, {%4,%5,%6,%7}, {%8,%9}, {%0,%1,%2,%3};\n"
        : "+f"(c[0]), "+f"(c[1]), "+f"(c[2]), "+f"(c[3])
        : "r"(a[0]), "r"(a[1]), "r"(a[2]), "r"(a[3]), "r"(b0), "r"(b1));
}
// fp16 accumulate variant: D/C are 2 x .f16x2 regs (half2 row r, half2 row r+8)
__device__ __forceinline__ void mma16h(uint32_t* c, const uint32_t* a, uint32_t b0, uint32_t b1) {
    asm("mma.sync.aligned.m16n8k16.row.col.f16.f16.f16.f16 "
        "{%0,%1}, {%2,%3,%4,%5}, {%6,%7}, {%0,%1};\n"
        : "+r"(c[0]), "+r"(c[1])
        : "r"(a[0]), "r"(a[1]), "r"(a[2]), "r"(a[3]), "r"(b0), "r"(b1));
}
__device__ __forceinline__ void ldsm4(uint32_t* d, uint32_t a) {
    asm volatile("ldmatrix.sync.aligned.m8n8.x4.shared.b16 {%0,%1,%2,%3}, [%4];\n"
        : "=r"(d[0]), "=r"(d[1]), "=r"(d[2]), "=r"(d[3]) : "r"(a));
}
__device__ __forceinline__ uint32_t s2u(const void* p) {
    return (uint32_t)__cvta_generic_to_shared(p);
}
__device__ __forceinline__ void cpa16(uint32_t dst, const void* src) {
    asm volatile("cp.async.cg.shared.global [%0], [%1], 16;\n" :: "r"(dst), "l"(src));
}
__device__ __forceinline__ void cpcommit() {
    asm volatile("cp.async.commit_group;\n" ::: "memory");
}
#define CPWAIT(n) asm volatile("cp.async.wait_group %0;\n" :: "n"(n) : "memory")

// fp16 LDSM lane offsets (bytes). strideB = row stride in bytes.
__device__ __forceinline__ uint32_t a_off16(int lane, int strideB) {
    return (uint32_t)(((lane & 7) + ((lane >> 3) & 1) * 8) * strideB + (lane >> 4) * 16);
}
__device__ __forceinline__ uint32_t b_off16(int lane, int strideB) {
    return (uint32_t)(((lane & 7) + ((lane >> 4) & 1) * 8) * strideB + ((lane >> 3) & 1) * 16);
}

#define STRB 144      // 72 halves per smem row (K/Q tiles)
#define STRV 272      // 136 halves per smem row (V tile, BN=128)

// ---------------------------------------------------------------------------
// Fused prologue: blocks [0,1024) convert weights; blocks [1024,1600)
// transpose+convert x [b][c][hw] -> g_xt [b][hw][c] fp16 (64x64 tiles).
// ---------------------------------------------------------------------------
__global__ __launch_bounds__(256) void prep(const float4* __restrict__ wq,
                                            const float4* __restrict__ wp,
                                            const float* __restrict__ x) {
    __shared__ float sT[64 * 65];
    const int tid = threadIdx.x;
    if (blockIdx.x < 1024) {
        int i = blockIdx.x * 256 + tid;
        float4 v; __half* dst;
        if (i < 196608) { v = wq[i];          dst = g_wq + i * 4; }
        else            { v = wp[i - 196608]; dst = g_wp + (i - 196608) * 4; }
        *(__half2*)dst       = __floats2half2_rn(v.x, v.y);
        *(__half2*)(dst + 2) = __floats2half2_rn(v.z, v.w);
        return;
    }
    const int bid = blockIdx.x - 1024;               // 576 tiles: 9 x 8 x 8
    const int hw0 = (bid % 9) * 64;
    const int c0  = ((bid / 9) & 7) * 64;
    const int b   = bid / 72;
#pragma unroll
    for (int rr = 0; rr < 4; rr++) {
        int f = tid + rr * 256, row = f >> 4, h4 = (f & 15) * 4;
        float4 v = *(const float4*)&x[((b * CIN) + c0 + row) * HW + hw0 + h4];
        sT[row * 65 + h4 + 0] = v.x; sT[row * 65 + h4 + 1] = v.y;
        sT[row * 65 + h4 + 2] = v.z; sT[row * 65 + h4 + 3] = v.w;
    }
    __syncthreads();
    {
        int f = tid, hwr = f >> 2, cc = (f & 3) * 16;   // 256 items exactly
        __half* dst = g_xt + ((b * HW) + hw0 + hwr) * CIN + c0 + cc;
#pragma unroll
        for (int j = 0; j < 8; j++)
            *(__half2*)(dst + 2 * j) =
                __floats2half2_rn(sT[(cc + 2 * j) * 65 + hwr], sT[(cc + 2 * j + 1) * 65 + hwr]);
    }
}

// ---------------------------------------------------------------------------
// Kernel A: QKV. D[m=hw 64][n=o 128] = X[hw][c] @ W[o][c]^T, K=512, BK=64.
// ---------------------------------------------------------------------------
__global__ __launch_bounds__(256, 3) void qkv_mma() {
    extern __shared__ __half smh[];
    const uint32_t sXb = s2u(smh);
    const uint32_t sWb = sXb + 2 * 4608 * 2;
    const int tid = threadIdx.x, wp = tid >> 5, lane = tid & 31;
    const int r = lane >> 2, q = lane & 3;
    const int wm = wp >> 2, wn = wp & 3;
    const int hw0 = blockIdx.x * 64, o0 = blockIdx.y * 128, b = blockIdx.z;
    const uint32_t aof = a_off16(lane, STRB), bof = b_off16(lane, STRB);

#define QKV_PF(K0, BUF) {                                                       \
    _Pragma("unroll") for (int rr = 0; rr < 2; rr++) {                          \
        int f = tid + rr * 256, row = f >> 3, ch = (f & 7) * 8;                 \
        cpa16(sXb + (uint32_t)((BUF) * 4608 + row * 72 + ch) * 2u,              \
              g_xt + ((b * HW) + hw0 + row) * CIN + (K0) + ch);                 \
    }                                                                           \
    _Pragma("unroll") for (int rr = 0; rr < 4; rr++) {                          \
        int f = tid + rr * 256, row = f >> 3, ch = (f & 7) * 8;                 \
        cpa16(sWb + (uint32_t)((BUF) * 9216 + row * 72 + ch) * 2u,              \
              g_wq + (o0 + row) * CIN + (K0) + ch);                             \
    }                                                                           \
    cpcommit(); }

    QKV_PF(0, 0);
    float acc[2][4][4] = {};

    for (int kk = 0; kk < 8; kk++) {
        const int buf = kk & 1;
        CPWAIT(0);
        __syncthreads();
        if (kk + 1 < 8) QKV_PF((kk + 1) * 64, buf ^ 1);

        const uint32_t xa = sXb + (uint32_t)(buf * 4608 + wm * 32 * 72) * 2u + aof;
        const uint32_t wa = sWb + (uint32_t)(buf * 9216 + wn * 32 * 72) * 2u + bof;
#pragma unroll
        for (int s = 0; s < 4; s++) {
            uint32_t aX[2][4];
            ldsm4(aX[0], xa + s * 32);
            ldsm4(aX[1], xa + 16 * STRB + s * 32);
#pragma unroll
            for (int j2 = 0; j2 < 2; j2++) {
                uint32_t bb[4]; ldsm4(bb, wa + j2 * 16 * STRB + s * 32);
#pragma unroll
                for (int mi = 0; mi < 2; mi++) {
                    mma16(acc[mi][j2 * 2],     aX[mi], bb[0], bb[1]);
                    mma16(acc[mi][j2 * 2 + 1], aX[mi], bb[2], bb[3]);
                }
            }
        }
    }

    const int g2 = b >> 2, vv = b & 3;
#pragma unroll
    for (int mi = 0; mi < 2; mi++) {
        int hwr = hw0 + wm * 32 + mi * 16 + r;
        int n0t = vv * HW + hwr, n1t = n0t + 8;
#pragma unroll
        for (int nj = 0; nj < 4; nj++) {
            int o = o0 + wn * 32 + nj * 8 + 2 * q;
            int head = o / 192, rem = o - head * 192, which = rem >> 6, d = rem & 63;
            int pp = g2 * 8 + head;
            float c0 = acc[mi][nj][0], c1 = acc[mi][nj][1];
            float c2 = acc[mi][nj][2], c3 = acc[mi][nj][3];
            if (which == 0) {
                *(__half2*)&g_q[(pp * NTOK + n0t) * HD + d] = __floats2half2_rn(c0 * QSCALE, c1 * QSCALE);
                *(__half2*)&g_q[(pp * NTOK + n1t) * HD + d] = __floats2half2_rn(c2 * QSCALE, c3 * QSCALE);
            } else if (which == 1) {
                *(__half2*)&g_k[(pp * NTOK + n0t) * HD + d] = __floats2half2_rn(c0, c1);
                *(__half2*)&g_k[(pp * NTOK + n1t) * HD + d] = __floats2half2_rn(c2, c3);
            } else {
                g_v[(pp * HD + d) * NTOK + n0t]     = __float2half_rn(c0);
                g_v[(pp * HD + d + 1) * NTOK + n0t] = __float2half_rn(c1);
                g_v[(pp * HD + d) * NTOK + n1t]     = __float2half_rn(c2);
                g_v[(pp * HD + d + 1) * NTOK + n1t] = __float2half_rn(c3);
            }
        }
    }
}

// ---------------------------------------------------------------------------
// Kernel B: flash attention fp16, round-8 inner loop, BN=128 (18 iterations).
// 4 warps x m32 strips, BM=128. S fp16-acc; n in four sequential 32-halves;
// P register-resident; l via ones-mma. 2-stage cp.async ring.
// smem: sQ [128][72]h | sK 2x[128][72]h | sV 2x[64][136]h = 90112 B.
// grid (18, 16), 128 thr, 2 CTAs/SM.
// ---------------------------------------------------------------------------
__global__ __launch_bounds__(128, 2) void flash_mma() {
    extern __shared__ __half smh[];
    const uint32_t sQb = s2u(smh);
    const uint32_t sKb = sQb + 128 * 72 * 2;
    const uint32_t sVb = sKb + 2 * 9216 * 2;

    const int tid = threadIdx.x, wm = tid >> 5, lane = tid & 31;
    const int r = lane >> 2, q = lane & 3;
    const int p = blockIdx.y, m0 = blockIdx.x * 128;

    const __half* Qb = g_q + (p * NTOK + m0) * HD;
    const __half* Kb = g_k + p * NTOK * HD;
    const __half* Vb = g_v + p * HD * NTOK;

    const uint32_t aof = a_off16(lane, STRB);
    const uint32_t bofK = b_off16(lane, STRB);
    const uint32_t bofV = b_off16(lane, STRV);

// one stage = 128 K-rows x 64 d  +  64 V-rows x 128 n
#define FL_PF(N0, BUF) {                                                        \
    _Pragma("unroll") for (int rr = 0; rr < 8; rr++) {                          \
        int f = tid + rr * 128, row = f >> 3, ch = (f & 7) * 8;                 \
        cpa16(sKb + (uint32_t)((BUF) * 9216 + row * 72 + ch) * 2u,              \
              Kb + ((N0) + row) * HD + ch);                                     \
    }                                                                           \
    _Pragma("unroll") for (int rr = 0; rr < 8; rr++) {                          \
        int f = tid + rr * 128, row = f >> 4, ch = (f & 15) * 8;                \
        cpa16(sVb + (uint32_t)((BUF) * 8704 + row * 136 + ch) * 2u,             \
              Vb + row * NTOK + (N0) + ch);                                     \
    }                                                                           \
    cpcommit(); }

    // stage Q (128 rows x 64 halves) + first K/V stage
#pragma unroll
    for (int rr = 0; rr < 8; rr++) {
        int f = tid + rr * 128, row = f >> 3, ch = (f & 7) * 8;
        cpa16(sQb + (uint32_t)(row * 72 + ch) * 2u, Qb + row * HD + ch);
    }
    cpcommit();
    FL_PF(0, 0);

    CPWAIT(0);            // Q + stage0 ready
    __syncthreads();
    uint32_t qf[2][4][4];
#pragma unroll
    for (int st = 0; st < 2; st++) {
        const uint32_t qa = sQb + (uint32_t)((wm * 32 + st * 16) * 72) * 2u + aof;
#pragma unroll
        for (int s = 0; s < 4; s++) ldsm4(qf[st][s], qa + s * 32);
    }

    float rO[2][8][4] = {};     // [strip][d-tile][4]
    float lacc[2][4] = {};      // row sums via ones-mma (fp32 acc)

    for (int it = 0; it < 18; it++) {
        const int buf = it & 1;
        if (it) { CPWAIT(0); __syncthreads(); }
        if (it + 1 < 18) FL_PF((it + 1) * 128, buf ^ 1);

        const uint32_t ka = sKb + (uint32_t)(buf * 9216) * 2u + bofK;
        const uint32_t va = sVb + (uint32_t)(buf * 8704) * 2u + bofV;

#pragma unroll
        for (int h = 0; h < 4; h++) {     // n in four 32-halves (sequential)
            // S(m32 x n32) = Q K^T, fp16 accumulate.
            uint32_t Sh[2][4][2] = {};
#pragma unroll
            for (int s = 0; s < 4; s++)
#pragma unroll
                for (int jn = 0; jn < 2; jn++) {
                    uint32_t bb[4];
                    ldsm4(bb, ka + (uint32_t)((h * 32 + jn * 16) * STRB) + s * 32);
#pragma unroll
                    for (int st = 0; st < 2; st++) {
                        mma16h(Sh[st][jn * 2],     qf[st][s], bb[0], bb[1]);
                        mma16h(Sh[st][jn * 2 + 1], qf[st][s], bb[2], bb[3]);
                    }
                }

            // p = exp2(S) directly on fp16 mma outputs; l += P @ ones
            uint32_t pf[2][2][4];
#pragma unroll
            for (int st = 0; st < 2; st++)
#pragma unroll
                for (int t = 0; t < 2; t++) {
                    __half2 e0 = h2exp2(*(__half2*)&Sh[st][2 * t][0]);
                    __half2 e1 = h2exp2(*(__half2*)&Sh[st][2 * t][1]);
                    __half2 e2 = h2exp2(*(__half2*)&Sh[st][2 * t + 1][0]);
                    __half2 e3 = h2exp2(*(__half2*)&Sh[st][2 * t + 1][1]);
                    pf[st][t][0] = *(uint32_t*)&e0;
                    pf[st][t][1] = *(uint32_t*)&e1;
                    pf[st][t][2] = *(uint32_t*)&e2;
                    pf[st][t][3] = *(uint32_t*)&e3;
                    mma16(lacc[st], pf[st][t], ONES, ONES);
                }

            // O(m32 x d64) += P @ V
#pragma unroll
            for (int t = 0; t < 2; t++)
#pragma unroll
                for (int j = 0; j < 4; j++) {
                    uint32_t bb[4];
                    ldsm4(bb, va + (uint32_t)(j * 16 * STRV) + (h * 32 + t * 16) * 2);
#pragma unroll
                    for (int st = 0; st < 2; st++) {
                        mma16(rO[st][2 * j],     pf[st][t], bb[0], bb[1]);
                        mma16(rO[st][2 * j + 1], pf[st][t], bb[2], bb[3]);
                    }
                }
        }
    }

    // epilogue: normalize, write g_ao [b][hw][c] fp16
    const int head = p & 7, gi = p >> 3;
#pragma unroll
    for (int st = 0; st < 2; st++) {
        const float i0 = 1.f / lacc[st][0], i1 = 1.f / lacc[st][2];
        const int row0 = m0 + wm * 32 + st * 16 + r, row1 = row0 + 8;
        const int v0 = row0 / HW, v1 = row1 / HW;
        __half* o0p = g_ao + ((gi * 4 + v0) * HW + (row0 - v0 * HW)) * CIN + head * 64;
        __half* o1p = g_ao + ((gi * 4 + v1) * HW + (row1 - v1 * HW)) * CIN + head * 64;
#pragma unroll
        for (int dt = 0; dt < 8; dt++) {
            *(__half2*)&o0p[dt * 8 + 2 * q] =
                __floats2half2_rn(rO[st][dt][0] * i0, rO[st][dt][1] * i0);
            *(__half2*)&o1p[dt * 8 + 2 * q] =
                __floats2half2_rn(rO[st][dt][2] * i1, rO[st][dt][3] * i1);
        }
    }
}

// ---------------------------------------------------------------------------
// Kernel C: proj + bias. D[m=o 128][n=hw 64] = W[o][c] @ AO[hw][c]^T.
// ---------------------------------------------------------------------------
__global__ __launch_bounds__(256, 3) void proj_mma(const float* __restrict__ bias,
                                                   float* __restrict__ out) {
    extern __shared__ __half smh[];
    const uint32_t sWb = s2u(smh);
    const uint32_t sBb = sWb + 2 * 9216 * 2;
    const int tid = threadIdx.x, wp = tid >> 5, lane = tid & 31;
    const int r = lane >> 2, q = lane & 3;
    const int wm = wp >> 1, wn = wp & 1;
    const int o0 = blockIdx.x * 128, hw0 = blockIdx.y * 64, b = blockIdx.z;
    const uint32_t aof = a_off16(lane, STRB), bof = b_off16(lane, STRB);

#define PRJ_PF(K0, BUF) {                                                       \
    _Pragma("unroll") for (int rr = 0; rr < 4; rr++) {                          \
        int f = tid + rr * 256, row = f >> 3, ch = (f & 7) * 8;                 \
        cpa16(sWb + (uint32_t)((BUF) * 9216 + row * 72 + ch) * 2u,              \
              g_wp + (o0 + row) * CIN + (K0) + ch);                             \
    }                                                                           \
    _Pragma("unroll") for (int rr = 0; rr < 2; rr++) {                          \
        int f = tid + rr * 256, row = f >> 3, ch = (f & 7) * 8;                 \
        cpa16(sBb + (uint32_t)((BUF) * 4608 + row * 72 + ch) * 2u,              \
              g_ao + ((b * HW) + hw0 + row) * CIN + (K0) + ch);                 \
    }                                                                           \
    cpcommit(); }

    PRJ_PF(0, 0);
    float acc[2][4][4] = {};

    for (int kk = 0; kk < 8; kk++) {
        const int buf = kk & 1;
        CPWAIT(0);
        __syncthreads();
        if (kk + 1 < 8) PRJ_PF((kk + 1) * 64, buf ^ 1);

        const uint32_t wa = sWb + (uint32_t)(buf * 9216 + wm * 32 * 72) * 2u + aof;
        const uint32_t xa = sBb + (uint32_t)(buf * 4608 + wn * 32 * 72) * 2u + bof;
#pragma unroll
        for (int s = 0; s < 4; s++) {
            uint32_t aW[2][4];
            ldsm4(aW[0], wa + s * 32);
            ldsm4(aW[1], wa + 16 * STRB + s * 32);
#pragma unroll
            for (int j2 = 0; j2 < 2; j2++) {
                uint32_t bb[4]; ldsm4(bb, xa + j2 * 16 * STRB + s * 32);
#pragma unroll
                for (int mi = 0; mi < 2; mi++) {
                    mma16(acc[mi][j2 * 2],     aW[mi], bb[0], bb[1]);
                    mma16(acc[mi][j2 * 2 + 1], aW[mi], bb[2], bb[3]);
                }
            }
        }
    }

#pragma unroll
    for (int mi = 0; mi < 2; mi++) {
        int o_r = o0 + wm * 32 + mi * 16 + r;
        float bv0 = bias[o_r], bv1 = bias[o_r + 8];
#pragma unroll
        for (int nj = 0; nj < 4; nj++) {
            int hw = hw0 + wn * 32 + nj * 8 + 2 * q;
            *(float2*)&out[(b * CIN + o_r) * HW + hw] =
                make_float2(acc[mi][nj][0] + bv0, acc[mi][nj][1] + bv0);
            *(float2*)&out[(b * CIN + o_r + 8) * HW + hw] =
                make_float2(acc[mi][nj][2] + bv1, acc[mi][nj][3] + bv1);
        }
    }
}

// ---------------------------------------------------------------------------
extern "C" void kernel_launch(void* const* d_in, const int* in_sizes, int n_in,
                              void* d_out, int out_size) {
    const float* x      = (const float*)d_in[0];
    const float* w_qkv  = (const float*)d_in[1];
    const float* w_proj = (const float*)d_in[2];
    const float* b_proj = (const float*)d_in[3];
    float* out = (float*)d_out;

    cudaFuncSetAttribute(qkv_mma,   cudaFuncAttributeMaxDynamicSharedMemorySize, 55296);
    cudaFuncSetAttribute(flash_mma, cudaFuncAttributeMaxDynamicSharedMemorySize, 90112);
    cudaFuncSetAttribute(proj_mma,  cudaFuncAttributeMaxDynamicSharedMemorySize, 55296);

    prep<<<1600, 256>>>((const float4*)w_qkv, (const float4*)w_proj, x);
    qkv_mma<<<dim3(9, 12, 8), 256, 55296>>>();
    flash_mma<<<dim3(18, 16), 128, 90112>>>();
    proj_mma<<<dim3(4, 9, 8), 256, 55296>>>(b_proj, out);
}

// round 14
// speedup vs baseline: 1.5220x; 1.0021x over previous
#include <cuda_runtime.h>
#include <cuda_fp16.h>
#include <cstdint>

#define HW     576
#define CIN    512
#define HD     64
#define NTOK   2304      // V_NUM * HW
#define NPAIR  16        // groups(2) * heads(8)
#define NB     8
#define QSCALE (0.125f * 1.4426950408889634f)   // hd^-0.5 * log2(e)

// Scratch (device globals: allocation-free rule). All fp16.
__device__ __align__(16) __half g_xt[NB * HW * CIN];     // x transposed [b][hw][c]
__device__ __align__(16) __half g_wq[3 * CIN * CIN];     // w_qkv [o][c]
__device__ __align__(16) __half g_wp[CIN * CIN];         // w_proj [o][c]
__device__ __align__(16) __half g_q[NPAIR * NTOK * HD];  // [p][n][d], scale folded
__device__ __align__(16) __half g_k[NPAIR * NTOK * HD];  // [p][n][d]
__device__ __align__(16) __half g_v[NPAIR * HD * NTOK];  // [p][d][n]
__device__ __align__(16) __half g_ao[NB * HW * CIN];     // attn out [b][hw][c]

// ---------------- helpers ----------------
__device__ __forceinline__ void mma16(float* c, const uint32_t* a, uint32_t b0, uint32_t b1) {
    asm("mma.sync.aligned.m16n8k16.row.col.f32.f16.f16.f32 "
        "{%0,%1,%2,%3}, {%4,%5,%6,%7}, {%8,%9}, {%0,%1,%2,%3};\n"
        : "+f"(c[0]), "+f"(c[1]), "+f"(c[2]), "+f"(c[3])
        : "r"(a[0]), "r"(a[1]), "r"(a[2]), "r"(a[3]), "r"(b0), "r"(b1));
}
// fp16 accumulate variant: D/C are 2 x .f16x2 regs (half2 row r, half2 row r+8)
__device__ __forceinline__ void mma16h(uint32_t* c, const uint32_t* a, uint32_t b0, uint32_t b1) {
    asm("mma.sync.aligned.m16n8k16.row.col.f16.f16.f16.f16 "
        "{%0,%1}, {%2,%3,%4,%5}, {%6,%7}, {%0,%1};\n"
        : "+r"(c[0]), "+r"(c[1])
        : "r"(a[0]), "r"(a[1]), "r"(a[2]), "r"(a[3]), "r"(b0), "r"(b1));
}
__device__ __forceinline__ void ldsm4(uint32_t* d, uint32_t a) {
    asm volatile("ldmatrix.sync.aligned.m8n8.x4.shared.b16 {%0,%1,%2,%3}, [%4];\n"
        : "=r"(d[0]), "=r"(d[1]), "=r"(d[2]), "=r"(d[3]) : "r"(a));
}
__device__ __forceinline__ uint32_t s2u(const void* p) {
    return (uint32_t)__cvta_generic_to_shared(p);
}
__device__ __forceinline__ void cpa16(uint32_t dst, const void* src) {
    asm volatile("cp.async.cg.shared.global [%0], [%1], 16;\n" :: "r"(dst), "l"(src));
}
__device__ __forceinline__ void cpcommit() {
    asm volatile("cp.async.commit_group;\n" ::: "memory");
}
#define CPWAIT(n) asm volatile("cp.async.wait_group %0;\n" :: "n"(n) : "memory")

// fp16 LDSM lane offsets (bytes). strideB = row stride in bytes.
__device__ __forceinline__ uint32_t a_off16(int lane, int strideB) {
    return (uint32_t)(((lane & 7) + ((lane >> 3) & 1) * 8) * strideB + (lane >> 4) * 16);
}
__device__ __forceinline__ uint32_t b_off16(int lane, int strideB) {
    return (uint32_t)(((lane & 7) + ((lane >> 4) & 1) * 8) * strideB + ((lane >> 3) & 1) * 16);
}

#define STRB 144      // 72 halves per smem row
#define H2(u) (*(__half2*)&(u))

// ---------------------------------------------------------------------------
// Fused prologue: blocks [0,1024) convert weights; blocks [1024,1600)
// transpose+convert x [b][c][hw] -> g_xt [b][hw][c] fp16 (64x64 tiles).
// ---------------------------------------------------------------------------
__global__ __launch_bounds__(256) void prep(const float4* __restrict__ wq,
                                            const float4* __restrict__ wp,
                                            const float* __restrict__ x) {
    __shared__ float sT[64 * 65];
    const int tid = threadIdx.x;
    if (blockIdx.x < 1024) {
        int i = blockIdx.x * 256 + tid;
        float4 v; __half* dst;
        if (i < 196608) { v = wq[i];          dst = g_wq + i * 4; }
        else            { v = wp[i - 196608]; dst = g_wp + (i - 196608) * 4; }
        *(__half2*)dst       = __floats2half2_rn(v.x, v.y);
        *(__half2*)(dst + 2) = __floats2half2_rn(v.z, v.w);
        return;
    }
    const int bid = blockIdx.x - 1024;               // 576 tiles: 9 x 8 x 8
    const int hw0 = (bid % 9) * 64;
    const int c0  = ((bid / 9) & 7) * 64;
    const int b   = bid / 72;
#pragma unroll
    for (int rr = 0; rr < 4; rr++) {
        int f = tid + rr * 256, row = f >> 4, h4 = (f & 15) * 4;
        float4 v = *(const float4*)&x[((b * CIN) + c0 + row) * HW + hw0 + h4];
        sT[row * 65 + h4 + 0] = v.x; sT[row * 65 + h4 + 1] = v.y;
        sT[row * 65 + h4 + 2] = v.z; sT[row * 65 + h4 + 3] = v.w;
    }
    __syncthreads();
    {
        int f = tid, hwr = f >> 2, cc = (f & 3) * 16;   // 256 items exactly
        __half* dst = g_xt + ((b * HW) + hw0 + hwr) * CIN + c0 + cc;
#pragma unroll
        for (int j = 0; j < 8; j++)
            *(__half2*)(dst + 2 * j) =
                __floats2half2_rn(sT[(cc + 2 * j) * 65 + hwr], sT[(cc + 2 * j + 1) * 65 + hwr]);
    }
}

// ---------------------------------------------------------------------------
// Kernel A: QKV. D[m=hw 64][n=o 128] = X[hw][c] @ W[o][c]^T, K=512, BK=64.
// ---------------------------------------------------------------------------
__global__ __launch_bounds__(256, 3) void qkv_mma() {
    extern __shared__ __half smh[];
    const uint32_t sXb = s2u(smh);
    const uint32_t sWb = sXb + 2 * 4608 * 2;
    const int tid = threadIdx.x, wp = tid >> 5, lane = tid & 31;
    const int r = lane >> 2, q = lane & 3;
    const int wm = wp >> 2, wn = wp & 3;
    const int hw0 = blockIdx.x * 64, o0 = blockIdx.y * 128, b = blockIdx.z;
    const uint32_t aof = a_off16(lane, STRB), bof = b_off16(lane, STRB);

#define QKV_PF(K0, BUF) {                                                       \
    _Pragma("unroll") for (int rr = 0; rr < 2; rr++) {                          \
        int f = tid + rr * 256, row = f >> 3, ch = (f & 7) * 8;                 \
        cpa16(sXb + (uint32_t)((BUF) * 4608 + row * 72 + ch) * 2u,              \
              g_xt + ((b * HW) + hw0 + row) * CIN + (K0) + ch);                 \
    }                                                                           \
    _Pragma("unroll") for (int rr = 0; rr < 4; rr++) {                          \
        int f = tid + rr * 256, row = f >> 3, ch = (f & 7) * 8;                 \
        cpa16(sWb + (uint32_t)((BUF) * 9216 + row * 72 + ch) * 2u,              \
              g_wq + (o0 + row) * CIN + (K0) + ch);                             \
    }                                                                           \
    cpcommit(); }

    QKV_PF(0, 0);
    float acc[2][4][4] = {};

    for (int kk = 0; kk < 8; kk++) {
        const int buf = kk & 1;
        CPWAIT(0);
        __syncthreads();
        if (kk + 1 < 8) QKV_PF((kk + 1) * 64, buf ^ 1);

        const uint32_t xa = sXb + (uint32_t)(buf * 4608 + wm * 32 * 72) * 2u + aof;
        const uint32_t wa = sWb + (uint32_t)(buf * 9216 + wn * 32 * 72) * 2u + bof;
#pragma unroll
        for (int s = 0; s < 4; s++) {
            uint32_t aX[2][4];
            ldsm4(aX[0], xa + s * 32);
            ldsm4(aX[1], xa + 16 * STRB + s * 32);
#pragma unroll
            for (int j2 = 0; j2 < 2; j2++) {
                uint32_t bb[4]; ldsm4(bb, wa + j2 * 16 * STRB + s * 32);
#pragma unroll
                for (int mi = 0; mi < 2; mi++) {
                    mma16(acc[mi][j2 * 2],     aX[mi], bb[0], bb[1]);
                    mma16(acc[mi][j2 * 2 + 1], aX[mi], bb[2], bb[3]);
                }
            }
        }
    }

    const int g2 = b >> 2, vv = b & 3;
#pragma unroll
    for (int mi = 0; mi < 2; mi++) {
        int hwr = hw0 + wm * 32 + mi * 16 + r;
        int n0t = vv * HW + hwr, n1t = n0t + 8;
#pragma unroll
        for (int nj = 0; nj < 4; nj++) {
            int o = o0 + wn * 32 + nj * 8 + 2 * q;
            int head = o / 192, rem = o - head * 192, which = rem >> 6, d = rem & 63;
            int pp = g2 * 8 + head;
            float c0 = acc[mi][nj][0], c1 = acc[mi][nj][1];
            float c2 = acc[mi][nj][2], c3 = acc[mi][nj][3];
            if (which == 0) {
                *(__half2*)&g_q[(pp * NTOK + n0t) * HD + d] = __floats2half2_rn(c0 * QSCALE, c1 * QSCALE);
                *(__half2*)&g_q[(pp * NTOK + n1t) * HD + d] = __floats2half2_rn(c2 * QSCALE, c3 * QSCALE);
            } else if (which == 1) {
                *(__half2*)&g_k[(pp * NTOK + n0t) * HD + d] = __floats2half2_rn(c0, c1);
                *(__half2*)&g_k[(pp * NTOK + n1t) * HD + d] = __floats2half2_rn(c2, c3);
            } else {
                g_v[(pp * HD + d) * NTOK + n0t]     = __float2half_rn(c0);
                g_v[(pp * HD + d + 1) * NTOK + n0t] = __float2half_rn(c1);
                g_v[(pp * HD + d) * NTOK + n1t]     = __float2half_rn(c2);
                g_v[(pp * HD + d + 1) * NTOK + n1t] = __float2half_rn(c3);
            }
        }
    }
}

// ---------------------------------------------------------------------------
// Kernel B: flash attention fp16 — round-8 structure (BM=128, 4 warps x m32,
// BN=64, 3-stage ring, S fp16-acc, P register-resident) with row sums moved
// to the FMA pipe (hadd2 pairs + fp32 acc; quad-shuffle in epilogue).
// grid (18, 16), 128 thr, 2 CTAs/SM.
// ---------------------------------------------------------------------------
__global__ __launch_bounds__(128, 2) void flash_mma() {
    extern __shared__ __half smh[];
    const uint32_t sQb = s2u(smh);
    const uint32_t sKb = sQb + 128 * 72 * 2;
    const uint32_t sVb = sKb + 3 * 4608 * 2;

    const int tid = threadIdx.x, wm = tid >> 5, lane = tid & 31;
    const int r = lane >> 2, q = lane & 3;
    const int p = blockIdx.y, m0 = blockIdx.x * 128;

    const __half* Qb = g_q + (p * NTOK + m0) * HD;
    const __half* Kb = g_k + p * NTOK * HD;
    const __half* Vb = g_v + p * HD * NTOK;

    const uint32_t aof = a_off16(lane, STRB), bof = b_off16(lane, STRB);

#define FL_PF(N0, BUF) {                                                        \
    _Pragma("unroll") for (int rr = 0; rr < 4; rr++) {                          \
        int f = tid + rr * 128, row = f >> 3, ch = (f & 7) * 8;                 \
        cpa16(sKb + (uint32_t)((BUF) * 4608 + row * 72 + ch) * 2u,              \
              Kb + ((N0) + row) * HD + ch);                                     \
        cpa16(sVb + (uint32_t)((BUF) * 4608 + row * 72 + ch) * 2u,              \
              Vb + row * NTOK + (N0) + ch);                                     \
    }                                                                           \
    cpcommit(); }

    // stage Q (128 rows x 64 halves), then first two K/V stages
#pragma unroll
    for (int rr = 0; rr < 8; rr++) {
        int f = tid + rr * 128, row = f >> 3, ch = (f & 7) * 8;
        cpa16(sQb + (uint32_t)(row * 72 + ch) * 2u, Qb + row * HD + ch);
    }
    cpcommit();
    FL_PF(0, 0);
    FL_PF(64, 1);

    CPWAIT(1);            // Q + stage0 ready
    __syncthreads();
    uint32_t qf[2][4][4];
#pragma unroll
    for (int st = 0; st < 2; st++) {
        const uint32_t qa = sQb + (uint32_t)((wm * 32 + st * 16) * 72) * 2u + aof;
#pragma unroll
        for (int s = 0; s < 4; s++) ldsm4(qf[st][s], qa + s * 32);
    }

    float rO[2][8][4] = {};     // [strip][d-tile][4]
    float sr[2]  = {0.f, 0.f};  // per-thread partial row sums (row r)
    float sr8[2] = {0.f, 0.f};  // (row r+8)

    for (int it = 0; it < 36; it++) {
        const int buf = it % 3;
        if (it) { CPWAIT(1); __syncthreads(); }
        if (it + 2 < 36) FL_PF((it + 2) * 64, (it + 2) % 3);

        const uint32_t ka = sKb + (uint32_t)(buf * 4608) * 2u + bof;
        const uint32_t va = sVb + (uint32_t)(buf * 4608) * 2u + bof;

#pragma unroll
        for (int h = 0; h < 2; h++) {     // n in two 32-halves (sequential)
            // S(m32 x n32) = Q K^T, fp16 accumulate.
            uint32_t Sh[2][4][2] = {};
#pragma unroll
            for (int s = 0; s < 4; s++)
#pragma unroll
                for (int jn = 0; jn < 2; jn++) {
                    uint32_t bb[4];
                    ldsm4(bb, ka + (uint32_t)((h * 32 + jn * 16) * STRB) + s * 32);
#pragma unroll
                    for (int st = 0; st < 2; st++) {
                        mma16h(Sh[st][jn * 2],     qf[st][s], bb[0], bb[1]);
                        mma16h(Sh[st][jn * 2 + 1], qf[st][s], bb[2], bb[3]);
                    }
                }

            // p = exp2(S) directly on fp16 mma outputs; row sums on FMA pipe
            uint32_t pf[2][2][4];
#pragma unroll
            for (int st = 0; st < 2; st++) {
#pragma unroll
                for (int t = 0; t < 2; t++) {
                    __half2 e0 = h2exp2(*(__half2*)&Sh[st][2 * t][0]);
                    __half2 e1 = h2exp2(*(__half2*)&Sh[st][2 * t][1]);
                    __half2 e2 = h2exp2(*(__half2*)&Sh[st][2 * t + 1][0]);
                    __half2 e3 = h2exp2(*(__half2*)&Sh[st][2 * t + 1][1]);
                    pf[st][t][0] = *(uint32_t*)&e0;
                    pf[st][t][1] = *(uint32_t*)&e1;
                    pf[st][t][2] = *(uint32_t*)&e2;
                    pf[st][t][3] = *(uint32_t*)&e3;
                }
                // row r lives in pf[.][0] and pf[.][2]; row r+8 in pf[.][1], pf[.][3]
                __half2 a0 = __hadd2(H2(pf[st][0][0]), H2(pf[st][1][0]));
                __half2 a1 = __hadd2(H2(pf[st][0][2]), H2(pf[st][1][2]));
                __half2 b0 = __hadd2(H2(pf[st][0][1]), H2(pf[st][1][1]));
                __half2 b1 = __hadd2(H2(pf[st][0][3]), H2(pf[st][1][3]));
                float2 fa0 = __half22float2(a0), fa1 = __half22float2(a1);
                float2 fb0 = __half22float2(b0), fb1 = __half22float2(b1);
                sr[st]  += (fa0.x + fa0.y) + (fa1.x + fa1.y);
                sr8[st] += (fb0.x + fb0.y) + (fb1.x + fb1.y);
            }

            // O(m32 x d64) += P @ V
#pragma unroll
            for (int t = 0; t < 2; t++)
#pragma unroll
                for (int j = 0; j < 4; j++) {
                    uint32_t bb[4];
                    ldsm4(bb, va + (uint32_t)(j * 16 * STRB) + (h * 32 + t * 16) * 2);
#pragma unroll
                    for (int st = 0; st < 2; st++) {
                        mma16(rO[st][2 * j],     pf[st][t], bb[0], bb[1]);
                        mma16(rO[st][2 * j + 1], pf[st][t], bb[2], bb[3]);
                    }
                }
        }
    }

    // epilogue: quad shuffle-reduce of row sums, normalize, write g_ao
    const int head = p & 7, gi = p >> 3;
#pragma unroll
    for (int st = 0; st < 2; st++) {
        float l0 = sr[st], l1 = sr8[st];
        l0 += __shfl_xor_sync(0xffffffffu, l0, 1);
        l0 += __shfl_xor_sync(0xffffffffu, l0, 2);
        l1 += __shfl_xor_sync(0xffffffffu, l1, 1);
        l1 += __shfl_xor_sync(0xffffffffu, l1, 2);
        const float i0 = 1.f / l0, i1 = 1.f / l1;
        const int row0 = m0 + wm * 32 + st * 16 + r, row1 = row0 + 8;
        const int v0 = row0 / HW, v1 = row1 / HW;
        __half* o0p = g_ao + ((gi * 4 + v0) * HW + (row0 - v0 * HW)) * CIN + head * 64;
        __half* o1p = g_ao + ((gi * 4 + v1) * HW + (row1 - v1 * HW)) * CIN + head * 64;
#pragma unroll
        for (int dt = 0; dt < 8; dt++) {
            *(__half2*)&o0p[dt * 8 + 2 * q] =
                __floats2half2_rn(rO[st][dt][0] * i0, rO[st][dt][1] * i0);
            *(__half2*)&o1p[dt * 8 + 2 * q] =
                __floats2half2_rn(rO[st][dt][2] * i1, rO[st][dt][3] * i1);
        }
    }
}

// ---------------------------------------------------------------------------
// Kernel C: proj + bias. D[m=o 128][n=hw 64] = W[o][c] @ AO[hw][c]^T.
// ---------------------------------------------------------------------------
__global__ __launch_bounds__(256, 3) void proj_mma(const float* __restrict__ bias,
                                                   float* __restrict__ out) {
    extern __shared__ __half smh[];
    const uint32_t sWb = s2u(smh);
    const uint32_t sBb = sWb + 2 * 9216 * 2;
    const int tid = threadIdx.x, wp = tid >> 5, lane = tid & 31;
    const int r = lane >> 2, q = lane & 3;
    const int wm = wp >> 1, wn = wp & 1;
    const int o0 = blockIdx.x * 128, hw0 = blockIdx.y * 64, b = blockIdx.z;
    const uint32_t aof = a_off16(lane, STRB), bof = b_off16(lane, STRB);

#define PRJ_PF(K0, BUF) {                                                       \
    _Pragma("unroll") for (int rr = 0; rr < 4; rr++) {                          \
        int f = tid + rr * 256, row = f >> 3, ch = (f & 7) * 8;                 \
        cpa16(sWb + (uint32_t)((BUF) * 9216 + row * 72 + ch) * 2u,              \
              g_wp + (o0 + row) * CIN + (K0) + ch);                             \
    }                                                                           \
    _Pragma("unroll") for (int rr = 0; rr < 2; rr++) {                          \
        int f = tid + rr * 256, row = f >> 3, ch = (f & 7) * 8;                 \
        cpa16(sBb + (uint32_t)((BUF) * 4608 + row * 72 + ch) * 2u,              \
              g_ao + ((b * HW) + hw0 + row) * CIN + (K0) + ch);                 \
    }                                                                           \
    cpcommit(); }

    PRJ_PF(0, 0);
    float acc[2][4][4] = {};

    for (int kk = 0; kk < 8; kk++) {
        const int buf = kk & 1;
        CPWAIT(0);
        __syncthreads();
        if (kk + 1 < 8) PRJ_PF((kk + 1) * 64, buf ^ 1);

        const uint32_t wa = sWb + (uint32_t)(buf * 9216 + wm * 32 * 72) * 2u + aof;
        const uint32_t xa = sBb + (uint32_t)(buf * 4608 + wn * 32 * 72) * 2u + bof;
#pragma unroll
        for (int s = 0; s < 4; s++) {
            uint32_t aW[2][4];
            ldsm4(aW[0], wa + s * 32);
            ldsm4(aW[1], wa + 16 * STRB + s * 32);
#pragma unroll
            for (int j2 = 0; j2 < 2; j2++) {
                uint32_t bb[4]; ldsm4(bb, xa + j2 * 16 * STRB + s * 32);
#pragma unroll
                for (int mi = 0; mi < 2; mi++) {
                    mma16(acc[mi][j2 * 2],     aW[mi], bb[0], bb[1]);
                    mma16(acc[mi][j2 * 2 + 1], aW[mi], bb[2], bb[3]);
                }
            }
        }
    }

#pragma unroll
    for (int mi = 0; mi < 2; mi++) {
        int o_r = o0 + wm * 32 + mi * 16 + r;
        float bv0 = bias[o_r], bv1 = bias[o_r + 8];
#pragma unroll
        for (int nj = 0; nj < 4; nj++) {
            int hw = hw0 + wn * 32 + nj * 8 + 2 * q;
            *(float2*)&out[(b * CIN + o_r) * HW + hw] =
                make_float2(acc[mi][nj][0] + bv0, acc[mi][nj][1] + bv0);
            *(float2*)&out[(b * CIN + o_r + 8) * HW + hw] =
                make_float2(acc[mi][nj][2] + bv1, acc[mi][nj][3] + bv1);
        }
    }
}

// ---------------------------------------------------------------------------
extern "C" void kernel_launch(void* const* d_in, const int* in_sizes, int n_in,
                              void* d_out, int out_size) {
    const float* x      = (const float*)d_in[0];
    const float* w_qkv  = (const float*)d_in[1];
    const float* w_proj = (const float*)d_in[2];
    const float* b_proj = (const float*)d_in[3];
    float* out = (float*)d_out;

    cudaFuncSetAttribute(qkv_mma,   cudaFuncAttributeMaxDynamicSharedMemorySize, 55296);
    cudaFuncSetAttribute(flash_mma, cudaFuncAttributeMaxDynamicSharedMemorySize, 73728);
    cudaFuncSetAttribute(proj_mma,  cudaFuncAttributeMaxDynamicSharedMemorySize, 55296);

    prep<<<1600, 256>>>((const float4*)w_qkv, (const float4*)w_proj, x);
    qkv_mma<<<dim3(9, 12, 8), 256, 55296>>>();
    flash_mma<<<dim3(18, 16), 128, 73728>>>();
    proj_mma<<<dim3(4, 9, 8), 256, 55296>>>(b_proj, out);
}

// round 15
// speedup vs baseline: 1.5827x; 1.0399x over previous
#include <cuda_runtime.h>
#include <cuda_fp16.h>
#include <cstdint>

#define HW     576
#define CIN    512
#define HD     64
#define NTOK   2304      // V_NUM * HW
#define NPAIR  16        // groups(2) * heads(8)
#define NB     8
#define QSCALE (0.125f * 1.4426950408889634f)   // hd^-0.5 * log2(e)

// Scratch (device globals: allocation-free rule). All fp16.
__device__ __align__(16) __half g_xt[NB * HW * CIN];     // x transposed [b][hw][c]
__device__ __align__(16) __half g_wq[3 * CIN * CIN];     // w_qkv [o][c]
__device__ __align__(16) __half g_wp[CIN * CIN];         // w_proj [o][c]
__device__ __align__(16) __half g_q[NPAIR * NTOK * HD];  // [p][n][d], scale folded
__device__ __align__(16) __half g_k[NPAIR * NTOK * HD];  // [p][n][d]
__device__ __align__(16) __half g_v[NPAIR * NTOK * HD];  // [p][n][d]  (coalesced now)
__device__ __align__(16) __half g_ao[NB * HW * CIN];     // attn out [b][hw][c]

// ---------------- helpers ----------------
__device__ __forceinline__ void mma16(float* c, const uint32_t* a, uint32_t b0, uint32_t b1) {
    asm("mma.sync.aligned.m16n8k16.row.col.f32.f16.f16.f32 "
        "{%0,%1,%2,%3}, {%4,%5,%6,%7}, {%8,%9}, {%0,%1,%2,%3};\n"
        : "+f"(c[0]), "+f"(c[1]), "+f"(c[2]), "+f"(c[3])
        : "r"(a[0]), "r"(a[1]), "r"(a[2]), "r"(a[3]), "r"(b0), "r"(b1));
}
// fp16 accumulate variant: D/C are 2 x .f16x2 regs (half2 row r, half2 row r+8)
__device__ __forceinline__ void mma16h(uint32_t* c, const uint32_t* a, uint32_t b0, uint32_t b1) {
    asm("mma.sync.aligned.m16n8k16.row.col.f16.f16.f16.f16 "
        "{%0,%1}, {%2,%3,%4,%5}, {%6,%7}, {%0,%1};\n"
        : "+r"(c[0]), "+r"(c[1])
        : "r"(a[0]), "r"(a[1]), "r"(a[2]), "r"(a[3]), "r"(b0), "r"(b1));
}
__device__ __forceinline__ void ldsm4(uint32_t* d, uint32_t a) {
    asm volatile("ldmatrix.sync.aligned.m8n8.x4.shared.b16 {%0,%1,%2,%3}, [%4];\n"
        : "=r"(d[0]), "=r"(d[1]), "=r"(d[2]), "=r"(d[3]) : "r"(a));
}
__device__ __forceinline__ void ldsm4t(uint32_t* d, uint32_t a) {
    asm volatile("ldmatrix.sync.aligned.m8n8.x4.trans.shared.b16 {%0,%1,%2,%3}, [%4];\n"
        : "=r"(d[0]), "=r"(d[1]), "=r"(d[2]), "=r"(d[3]) : "r"(a));
}
__device__ __forceinline__ uint32_t s2u(const void* p) {
    return (uint32_t)__cvta_generic_to_shared(p);
}
__device__ __forceinline__ void cpa16(uint32_t dst, const void* src) {
    asm volatile("cp.async.cg.shared.global [%0], [%1], 16;\n" :: "r"(dst), "l"(src));
}
__device__ __forceinline__ void cpcommit() {
    asm volatile("cp.async.commit_group;\n" ::: "memory");
}
#define CPWAIT(n) asm volatile("cp.async.wait_group %0;\n" :: "n"(n) : "memory")

// fp16 LDSM lane offsets (bytes). strideB = row stride in bytes.
__device__ __forceinline__ uint32_t a_off16(int lane, int strideB) {
    return (uint32_t)(((lane & 7) + ((lane >> 3) & 1) * 8) * strideB + (lane >> 4) * 16);
}
__device__ __forceinline__ uint32_t b_off16(int lane, int strideB) {
    return (uint32_t)(((lane & 7) + ((lane >> 4) & 1) * 8) * strideB + ((lane >> 3) & 1) * 16);
}
// trans B-frag offsets: matrices m0..m3 = [d0-7][n0-7],[d0-7][n8-15],
// [d8-15][n0-7],[d8-15][n8-15] from storage [n][d] -> swap bits 3/4 vs b_off16.
__device__ __forceinline__ uint32_t bt_off16(int lane, int strideB) {
    return (uint32_t)(((lane & 7) + ((lane >> 3) & 1) * 8) * strideB + ((lane >> 4) & 1) * 16);
}

#define STRB 144      // 72 halves per smem row
#define H2(u) (*(__half2*)&(u))

// ---------------------------------------------------------------------------
// Fused prologue: blocks [0,1024) convert weights; blocks [1024,1600)
// transpose+convert x [b][c][hw] -> g_xt [b][hw][c] fp16 (64x64 tiles).
// ---------------------------------------------------------------------------
__global__ __launch_bounds__(256) void prep(const float4* __restrict__ wq,
                                            const float4* __restrict__ wp,
                                            const float* __restrict__ x) {
    __shared__ float sT[64 * 65];
    const int tid = threadIdx.x;
    if (blockIdx.x < 1024) {
        int i = blockIdx.x * 256 + tid;
        float4 v; __half* dst;
        if (i < 196608) { v = wq[i];          dst = g_wq + i * 4; }
        else            { v = wp[i - 196608]; dst = g_wp + (i - 196608) * 4; }
        *(__half2*)dst       = __floats2half2_rn(v.x, v.y);
        *(__half2*)(dst + 2) = __floats2half2_rn(v.z, v.w);
        return;
    }
    const int bid = blockIdx.x - 1024;               // 576 tiles: 9 x 8 x 8
    const int hw0 = (bid % 9) * 64;
    const int c0  = ((bid / 9) & 7) * 64;
    const int b   = bid / 72;
#pragma unroll
    for (int rr = 0; rr < 4; rr++) {
        int f = tid + rr * 256, row = f >> 4, h4 = (f & 15) * 4;
        float4 v = *(const float4*)&x[((b * CIN) + c0 + row) * HW + hw0 + h4];
        sT[row * 65 + h4 + 0] = v.x; sT[row * 65 + h4 + 1] = v.y;
        sT[row * 65 + h4 + 2] = v.z; sT[row * 65 + h4 + 3] = v.w;
    }
    __syncthreads();
    {
        int f = tid, hwr = f >> 2, cc = (f & 3) * 16;   // 256 items exactly
        __half* dst = g_xt + ((b * HW) + hw0 + hwr) * CIN + c0 + cc;
#pragma unroll
        for (int j = 0; j < 8; j++)
            *(__half2*)(dst + 2 * j) =
                __floats2half2_rn(sT[(cc + 2 * j) * 65 + hwr], sT[(cc + 2 * j + 1) * 65 + hwr]);
    }
}

// ---------------------------------------------------------------------------
// Kernel A: QKV. D[m=hw 64][n=o 128] = X[hw][c] @ W[o][c]^T, K=512, BK=64.
// All three outputs now coalesced half2 stores ([p][n][d]).
// ---------------------------------------------------------------------------
__global__ __launch_bounds__(256, 3) void qkv_mma() {
    extern __shared__ __half smh[];
    const uint32_t sXb = s2u(smh);
    const uint32_t sWb = sXb + 2 * 4608 * 2;
    const int tid = threadIdx.x, wp = tid >> 5, lane = tid & 31;
    const int r = lane >> 2, q = lane & 3;
    const int wm = wp >> 2, wn = wp & 3;
    const int hw0 = blockIdx.x * 64, o0 = blockIdx.y * 128, b = blockIdx.z;
    const uint32_t aof = a_off16(lane, STRB), bof = b_off16(lane, STRB);

#define QKV_PF(K0, BUF) {                                                       \
    _Pragma("unroll") for (int rr = 0; rr < 2; rr++) {                          \
        int f = tid + rr * 256, row = f >> 3, ch = (f & 7) * 8;                 \
        cpa16(sXb + (uint32_t)((BUF) * 4608 + row * 72 + ch) * 2u,              \
              g_xt + ((b * HW) + hw0 + row) * CIN + (K0) + ch);                 \
    }                                                                           \
    _Pragma("unroll") for (int rr = 0; rr < 4; rr++) {                          \
        int f = tid + rr * 256, row = f >> 3, ch = (f & 7) * 8;                 \
        cpa16(sWb + (uint32_t)((BUF) * 9216 + row * 72 + ch) * 2u,              \
              g_wq + (o0 + row) * CIN + (K0) + ch);                             \
    }                                                                           \
    cpcommit(); }

    QKV_PF(0, 0);
    float acc[2][4][4] = {};

    for (int kk = 0; kk < 8; kk++) {
        const int buf = kk & 1;
        CPWAIT(0);
        __syncthreads();
        if (kk + 1 < 8) QKV_PF((kk + 1) * 64, buf ^ 1);

        const uint32_t xa = sXb + (uint32_t)(buf * 4608 + wm * 32 * 72) * 2u + aof;
        const uint32_t wa = sWb + (uint32_t)(buf * 9216 + wn * 32 * 72) * 2u + bof;
#pragma unroll
        for (int s = 0; s < 4; s++) {
            uint32_t aX[2][4];
            ldsm4(aX[0], xa + s * 32);
            ldsm4(aX[1], xa + 16 * STRB + s * 32);
#pragma unroll
            for (int j2 = 0; j2 < 2; j2++) {
                uint32_t bb[4]; ldsm4(bb, wa + j2 * 16 * STRB + s * 32);
#pragma unroll
                for (int mi = 0; mi < 2; mi++) {
                    mma16(acc[mi][j2 * 2],     aX[mi], bb[0], bb[1]);
                    mma16(acc[mi][j2 * 2 + 1], aX[mi], bb[2], bb[3]);
                }
            }
        }
    }

    const int g2 = b >> 2, vv = b & 3;
#pragma unroll
    for (int mi = 0; mi < 2; mi++) {
        int hwr = hw0 + wm * 32 + mi * 16 + r;
        int n0t = vv * HW + hwr, n1t = n0t + 8;
#pragma unroll
        for (int nj = 0; nj < 4; nj++) {
            int o = o0 + wn * 32 + nj * 8 + 2 * q;
            int head = o / 192, rem = o - head * 192, which = rem >> 6, d = rem & 63;
            int pp = g2 * 8 + head;
            float c0 = acc[mi][nj][0], c1 = acc[mi][nj][1];
            float c2 = acc[mi][nj][2], c3 = acc[mi][nj][3];
            __half* dst = (which == 0) ? g_q : (which == 1) ? g_k : g_v;
            float sc = (which == 0) ? QSCALE : 1.0f;
            *(__half2*)&dst[(pp * NTOK + n0t) * HD + d] = __floats2half2_rn(c0 * sc, c1 * sc);
            *(__half2*)&dst[(pp * NTOK + n1t) * HD + d] = __floats2half2_rn(c2 * sc, c3 * sc);
        }
    }
}

// ---------------------------------------------------------------------------
// Kernel B: flash attention fp16 — BM=128, 4 warps x m32, BN=64, 3-stage ring,
// S fp16-acc, P register-resident, FMA-pipe row sums. V tile stored [n][d]
// (same g2s as K) and fed to PV mma via ldmatrix.trans.
// grid (18, 16), 128 thr, 2 CTAs/SM.
// ---------------------------------------------------------------------------
__global__ __launch_bounds__(128, 2) void flash_mma() {
    extern __shared__ __half smh[];
    const uint32_t sQb = s2u(smh);
    const uint32_t sKb = sQb + 128 * 72 * 2;
    const uint32_t sVb = sKb + 3 * 4608 * 2;

    const int tid = threadIdx.x, wm = tid >> 5, lane = tid & 31;
    const int r = lane >> 2, q = lane & 3;
    const int p = blockIdx.y, m0 = blockIdx.x * 128;

    const __half* Qb = g_q + (p * NTOK + m0) * HD;
    const __half* Kb = g_k + p * NTOK * HD;
    const __half* Vb = g_v + p * NTOK * HD;

    const uint32_t aof = a_off16(lane, STRB);
    const uint32_t bof = b_off16(lane, STRB);
    const uint32_t btf = bt_off16(lane, STRB);

#define FL_PF(N0, BUF) {                                                        \
    _Pragma("unroll") for (int rr = 0; rr < 4; rr++) {                          \
        int f = tid + rr * 128, row = f >> 3, ch = (f & 7) * 8;                 \
        cpa16(sKb + (uint32_t)((BUF) * 4608 + row * 72 + ch) * 2u,              \
              Kb + ((N0) + row) * HD + ch);                                     \
        cpa16(sVb + (uint32_t)((BUF) * 4608 + row * 72 + ch) * 2u,              \
              Vb + ((N0) + row) * HD + ch);                                     \
    }                                                                           \
    cpcommit(); }

    // stage Q (128 rows x 64 halves), then first two K/V stages
#pragma unroll
    for (int rr = 0; rr < 8; rr++) {
        int f = tid + rr * 128, row = f >> 3, ch = (f & 7) * 8;
        cpa16(sQb + (uint32_t)(row * 72 + ch) * 2u, Qb + row * HD + ch);
    }
    cpcommit();
    FL_PF(0, 0);
    FL_PF(64, 1);

    CPWAIT(1);            // Q + stage0 ready
    __syncthreads();
    uint32_t qf[2][4][4];
#pragma unroll
    for (int st = 0; st < 2; st++) {
        const uint32_t qa = sQb + (uint32_t)((wm * 32 + st * 16) * 72) * 2u + aof;
#pragma unroll
        for (int s = 0; s < 4; s++) ldsm4(qf[st][s], qa + s * 32);
    }

    float rO[2][8][4] = {};     // [strip][d-tile][4]
    float sr[2]  = {0.f, 0.f};  // per-thread partial row sums (row r)
    float sr8[2] = {0.f, 0.f};  // (row r+8)

    for (int it = 0; it < 36; it++) {
        const int buf = it % 3;
        if (it) { CPWAIT(1); __syncthreads(); }
        if (it + 2 < 36) FL_PF((it + 2) * 64, (it + 2) % 3);

        const uint32_t ka = sKb + (uint32_t)(buf * 4608) * 2u + bof;
        const uint32_t va = sVb + (uint32_t)(buf * 4608) * 2u + btf;

#pragma unroll
        for (int h = 0; h < 2; h++) {     // n in two 32-halves (sequential)
            // S(m32 x n32) = Q K^T, fp16 accumulate.
            uint32_t Sh[2][4][2] = {};
#pragma unroll
            for (int s = 0; s < 4; s++)
#pragma unroll
                for (int jn = 0; jn < 2; jn++) {
                    uint32_t bb[4];
                    ldsm4(bb, ka + (uint32_t)((h * 32 + jn * 16) * STRB) + s * 32);
#pragma unroll
                    for (int st = 0; st < 2; st++) {
                        mma16h(Sh[st][jn * 2],     qf[st][s], bb[0], bb[1]);
                        mma16h(Sh[st][jn * 2 + 1], qf[st][s], bb[2], bb[3]);
                    }
                }

            // p = exp2(S) directly on fp16 mma outputs; row sums on FMA pipe
            uint32_t pf[2][2][4];
#pragma unroll
            for (int st = 0; st < 2; st++) {
#pragma unroll
                for (int t = 0; t < 2; t++) {
                    __half2 e0 = h2exp2(*(__half2*)&Sh[st][2 * t][0]);
                    __half2 e1 = h2exp2(*(__half2*)&Sh[st][2 * t][1]);
                    __half2 e2 = h2exp2(*(__half2*)&Sh[st][2 * t + 1][0]);
                    __half2 e3 = h2exp2(*(__half2*)&Sh[st][2 * t + 1][1]);
                    pf[st][t][0] = *(uint32_t*)&e0;
                    pf[st][t][1] = *(uint32_t*)&e1;
                    pf[st][t][2] = *(uint32_t*)&e2;
                    pf[st][t][3] = *(uint32_t*)&e3;
                }
                __half2 a0 = __hadd2(H2(pf[st][0][0]), H2(pf[st][1][0]));
                __half2 a1 = __hadd2(H2(pf[st][0][2]), H2(pf[st][1][2]));
                __half2 b0 = __hadd2(H2(pf[st][0][1]), H2(pf[st][1][1]));
                __half2 b1 = __hadd2(H2(pf[st][0][3]), H2(pf[st][1][3]));
                float2 fa0 = __half22float2(a0), fa1 = __half22float2(a1);
                float2 fb0 = __half22float2(b0), fb1 = __half22float2(b1);
                sr[st]  += (fa0.x + fa0.y) + (fa1.x + fa1.y);
                sr8[st] += (fb0.x + fb0.y) + (fb1.x + fb1.y);
            }

            // O(m32 x d64) += P @ V  (V tile [n][d], trans LDSM)
#pragma unroll
            for (int t = 0; t < 2; t++)
#pragma unroll
                for (int j = 0; j < 4; j++) {
                    uint32_t bb[4];
                    ldsm4t(bb, va + (uint32_t)((h * 32 + t * 16) * STRB) + j * 32);
#pragma unroll
                    for (int st = 0; st < 2; st++) {
                        mma16(rO[st][2 * j],     pf[st][t], bb[0], bb[1]);
                        mma16(rO[st][2 * j + 1], pf[st][t], bb[2], bb[3]);
                    }
                }
        }
    }

    // epilogue: quad shuffle-reduce of row sums, normalize, write g_ao
    const int head = p & 7, gi = p >> 3;
#pragma unroll
    for (int st = 0; st < 2; st++) {
        float l0 = sr[st], l1 = sr8[st];
        l0 += __shfl_xor_sync(0xffffffffu, l0, 1);
        l0 += __shfl_xor_sync(0xffffffffu, l0, 2);
        l1 += __shfl_xor_sync(0xffffffffu, l1, 1);
        l1 += __shfl_xor_sync(0xffffffffu, l1, 2);
        const float i0 = 1.f / l0, i1 = 1.f / l1;
        const int row0 = m0 + wm * 32 + st * 16 + r, row1 = row0 + 8;
        const int v0 = row0 / HW, v1 = row1 / HW;
        __half* o0p = g_ao + ((gi * 4 + v0) * HW + (row0 - v0 * HW)) * CIN + head * 64;
        __half* o1p = g_ao + ((gi * 4 + v1) * HW + (row1 - v1 * HW)) * CIN + head * 64;
#pragma unroll
        for (int dt = 0; dt < 8; dt++) {
            *(__half2*)&o0p[dt * 8 + 2 * q] =
                __floats2half2_rn(rO[st][dt][0] * i0, rO[st][dt][1] * i0);
            *(__half2*)&o1p[dt * 8 + 2 * q] =
                __floats2half2_rn(rO[st][dt][2] * i1, rO[st][dt][3] * i1);
        }
    }
}

// ---------------------------------------------------------------------------
// Kernel C: proj + bias. D[m=o 128][n=hw 64] = W[o][c] @ AO[hw][c]^T.
// ---------------------------------------------------------------------------
__global__ __launch_bounds__(256, 3) void proj_mma(const float* __restrict__ bias,
                                                   float* __restrict__ out) {
    extern __shared__ __half smh[];
    const uint32_t sWb = s2u(smh);
    const uint32_t sBb = sWb + 2 * 9216 * 2;
    const int tid = threadIdx.x, wp = tid >> 5, lane = tid & 31;
    const int r = lane >> 2, q = lane & 3;
    const int wm = wp >> 1, wn = wp & 1;
    const int o0 = blockIdx.x * 128, hw0 = blockIdx.y * 64, b = blockIdx.z;
    const uint32_t aof = a_off16(lane, STRB), bof = b_off16(lane, STRB);

#define PRJ_PF(K0, BUF) {                                                       \
    _Pragma("unroll") for (int rr = 0; rr < 4; rr++) {                          \
        int f = tid + rr * 256, row = f >> 3, ch = (f & 7) * 8;                 \
        cpa16(sWb + (uint32_t)((BUF) * 9216 + row * 72 + ch) * 2u,              \
              g_wp + (o0 + row) * CIN + (K0) + ch);                             \
    }                                                                           \
    _Pragma("unroll") for (int rr = 0; rr < 2; rr++) {                          \
        int f = tid + rr * 256, row = f >> 3, ch = (f & 7) * 8;                 \
        cpa16(sBb + (uint32_t)((BUF) * 4608 + row * 72 + ch) * 2u,              \
              g_ao + ((b * HW) + hw0 + row) * CIN + (K0) + ch);                 \
    }                                                                           \
    cpcommit(); }

    PRJ_PF(0, 0);
    float acc[2][4][4] = {};

    for (int kk = 0; kk < 8; kk++) {
        const int buf = kk & 1;
        CPWAIT(0);
        __syncthreads();
        if (kk + 1 < 8) PRJ_PF((kk + 1) * 64, buf ^ 1);

        const uint32_t wa = sWb + (uint32_t)(buf * 9216 + wm * 32 * 72) * 2u + aof;
        const uint32_t xa = sBb + (uint32_t)(buf * 4608 + wn * 32 * 72) * 2u + bof;
#pragma unroll
        for (int s = 0; s < 4; s++) {
            uint32_t aW[2][4];
            ldsm4(aW[0], wa + s * 32);
            ldsm4(aW[1], wa + 16 * STRB + s * 32);
#pragma unroll
            for (int j2 = 0; j2 < 2; j2++) {
                uint32_t bb[4]; ldsm4(bb, xa + j2 * 16 * STRB + s * 32);
#pragma unroll
                for (int mi = 0; mi < 2; mi++) {
                    mma16(acc[mi][j2 * 2],     aW[mi], bb[0], bb[1]);
                    mma16(acc[mi][j2 * 2 + 1], aW[mi], bb[2], bb[3]);
                }
            }
        }
    }

#pragma unroll
    for (int mi = 0; mi < 2; mi++) {
        int o_r = o0 + wm * 32 + mi * 16 + r;
        float bv0 = bias[o_r], bv1 = bias[o_r + 8];
#pragma unroll
        for (int nj = 0; nj < 4; nj++) {
            int hw = hw0 + wn * 32 + nj * 8 + 2 * q;
            *(float2*)&out[(b * CIN + o_r) * HW + hw] =
                make_float2(acc[mi][nj][0] + bv0, acc[mi][nj][1] + bv0);
            *(float2*)&out[(b * CIN + o_r + 8) * HW + hw] =
                make_float2(acc[mi][nj][2] + bv1, acc[mi][nj][3] + bv1);
        }
    }
}

// ---------------------------------------------------------------------------
extern "C" void kernel_launch(void* const* d_in, const int* in_sizes, int n_in,
                              void* d_out, int out_size) {
    const float* x      = (const float*)d_in[0];
    const float* w_qkv  = (const float*)d_in[1];
    const float* w_proj = (const float*)d_in[2];
    const float* b_proj = (const float*)d_in[3];
    float* out = (float*)d_out;

    cudaFuncSetAttribute(qkv_mma,   cudaFuncAttributeMaxDynamicSharedMemorySize, 55296);
    cudaFuncSetAttribute(flash_mma, cudaFuncAttributeMaxDynamicSharedMemorySize, 73728);
    cudaFuncSetAttribute(proj_mma,  cudaFuncAttributeMaxDynamicSharedMemorySize, 55296);

    prep<<<1600, 256>>>((const float4*)w_qkv, (const float4*)w_proj, x);
    qkv_mma<<<dim3(9, 12, 8), 256, 55296>>>();
    flash_mma<<<dim3(18, 16), 128, 73728>>>();
    proj_mma<<<dim3(4, 9, 8), 256, 55296>>>(b_proj, out);
}

// round 16
// speedup vs baseline: 1.6078x; 1.0158x over previous
#include <cuda_runtime.h>
#include <cuda_fp16.h>
#include <cstdint>

#define HW     576
#define CIN    512
#define HD     64
#define NTOK   2304      // V_NUM * HW
#define NPAIR  16        // groups(2) * heads(8)
#define NB     8
#define QSCALE (0.125f * 1.4426950408889634f)   // hd^-0.5 * log2(e)

// Scratch (device globals: allocation-free rule). All fp16.
__device__ __align__(16) __half g_xt[NB * HW * CIN];     // x transposed [b][hw][c]
__device__ __align__(16) __half g_wq[3 * CIN * CIN];     // w_qkv [o][c]
__device__ __align__(16) __half g_wp[CIN * CIN];         // w_proj [o][c]
__device__ __align__(16) __half g_q[NPAIR * NTOK * HD];  // [p][n][d], scale folded
__device__ __align__(16) __half g_k[NPAIR * NTOK * HD];  // [p][n][d]
__device__ __align__(16) __half g_v[NPAIR * NTOK * HD];  // [p][n][d]
__device__ __align__(16) __half g_ao[NB * HW * CIN];     // attn out [b][hw][c]

// ---------------- helpers ----------------
__device__ __forceinline__ void mma16(float* c, const uint32_t* a, uint32_t b0, uint32_t b1) {
    asm("mma.sync.aligned.m16n8k16.row.col.f32.f16.f16.f32 "
        "{%0,%1,%2,%3}, {%4,%5,%6,%7}, {%8,%9}, {%0,%1,%2,%3};\n"
        : "+f"(c[0]), "+f"(c[1]), "+f"(c[2]), "+f"(c[3])
        : "r"(a[0]), "r"(a[1]), "r"(a[2]), "r"(a[3]), "r"(b0), "r"(b1));
}
// fp16 accumulate variant: D/C are 2 x .f16x2 regs (half2 row r, half2 row r+8)
__device__ __forceinline__ void mma16h(uint32_t* c, const uint32_t* a, uint32_t b0, uint32_t b1) {
    asm("mma.sync.aligned.m16n8k16.row.col.f16.f16.f16.f16 "
        "{%0,%1}, {%2,%3,%4,%5}, {%6,%7}, {%0,%1};\n"
        : "+r"(c[0]), "+r"(c[1])
        : "r"(a[0]), "r"(a[1]), "r"(a[2]), "r"(a[3]), "r"(b0), "r"(b1));
}
__device__ __forceinline__ void ldsm4(uint32_t* d, uint32_t a) {
    asm volatile("ldmatrix.sync.aligned.m8n8.x4.shared.b16 {%0,%1,%2,%3}, [%4];\n"
        : "=r"(d[0]), "=r"(d[1]), "=r"(d[2]), "=r"(d[3]) : "r"(a));
}
__device__ __forceinline__ void ldsm4t(uint32_t* d, uint32_t a) {
    asm volatile("ldmatrix.sync.aligned.m8n8.x4.trans.shared.b16 {%0,%1,%2,%3}, [%4];\n"
        : "=r"(d[0]), "=r"(d[1]), "=r"(d[2]), "=r"(d[3]) : "r"(a));
}
__device__ __forceinline__ uint32_t s2u(const void* p) {
    return (uint32_t)__cvta_generic_to_shared(p);
}
__device__ __forceinline__ void cpa16(uint32_t dst, const void* src) {
    asm volatile("cp.async.cg.shared.global [%0], [%1], 16;\n" :: "r"(dst), "l"(src));
}
__device__ __forceinline__ void cpcommit() {
    asm volatile("cp.async.commit_group;\n" ::: "memory");
}
#define CPWAIT(n) asm volatile("cp.async.wait_group %0;\n" :: "n"(n) : "memory")

// fp16 LDSM lane offsets (bytes). strideB = row stride in bytes.
__device__ __forceinline__ uint32_t a_off16(int lane, int strideB) {
    return (uint32_t)(((lane & 7) + ((lane >> 3) & 1) * 8) * strideB + (lane >> 4) * 16);
}
__device__ __forceinline__ uint32_t b_off16(int lane, int strideB) {
    return (uint32_t)(((lane & 7) + ((lane >> 4) & 1) * 8) * strideB + ((lane >> 3) & 1) * 16);
}
// trans B-frag offsets (V tile stored [n][d]); swap bits 3/4 vs b_off16.
__device__ __forceinline__ uint32_t bt_off16(int lane, int strideB) {
    return (uint32_t)(((lane & 7) + ((lane >> 3) & 1) * 8) * strideB + ((lane >> 4) & 1) * 16);
}

#define STRB 144      // 72 halves per smem row
#define H2(u) (*(__half2*)&(u))

// ---------------------------------------------------------------------------
// Fused prologue: blocks [0,1024) convert weights; blocks [1024,1600)
// transpose+convert x [b][c][hw] -> g_xt [b][hw][c] fp16 (64x64 tiles).
// ---------------------------------------------------------------------------
__global__ __launch_bounds__(256) void prep(const float4* __restrict__ wq,
                                            const float4* __restrict__ wp,
                                            const float* __restrict__ x) {
    __shared__ float sT[64 * 65];
    const int tid = threadIdx.x;
    if (blockIdx.x < 1024) {
        int i = blockIdx.x * 256 + tid;
        float4 v; __half* dst;
        if (i < 196608) { v = wq[i];          dst = g_wq + i * 4; }
        else            { v = wp[i - 196608]; dst = g_wp + (i - 196608) * 4; }
        *(__half2*)dst       = __floats2half2_rn(v.x, v.y);
        *(__half2*)(dst + 2) = __floats2half2_rn(v.z, v.w);
        return;
    }
    const int bid = blockIdx.x - 1024;               // 576 tiles: 9 x 8 x 8
    const int hw0 = (bid % 9) * 64;
    const int c0  = ((bid / 9) & 7) * 64;
    const int b   = bid / 72;
#pragma unroll
    for (int rr = 0; rr < 4; rr++) {
        int f = tid + rr * 256, row = f >> 4, h4 = (f & 15) * 4;
        float4 v = *(const float4*)&x[((b * CIN) + c0 + row) * HW + hw0 + h4];
        sT[row * 65 + h4 + 0] = v.x; sT[row * 65 + h4 + 1] = v.y;
        sT[row * 65 + h4 + 2] = v.z; sT[row * 65 + h4 + 3] = v.w;
    }
    __syncthreads();
    {
        int f = tid, hwr = f >> 2, cc = (f & 3) * 16;   // 256 items exactly
        __half* dst = g_xt + ((b * HW) + hw0 + hwr) * CIN + c0 + cc;
#pragma unroll
        for (int j = 0; j < 8; j++)
            *(__half2*)(dst + 2 * j) =
                __floats2half2_rn(sT[(cc + 2 * j) * 65 + hwr], sT[(cc + 2 * j + 1) * 65 + hwr]);
    }
}

// ---------------------------------------------------------------------------
// Kernel A: QKV. D[m=hw 64][n=o 128] = X[hw][c] @ W[o][c]^T, K=512, BK=64.
// 3-stage cp.async pipeline (prefetch 2 ahead). smem 82944 B, 2 CTAs/SM.
// ---------------------------------------------------------------------------
__global__ __launch_bounds__(256, 2) void qkv_mma() {
    extern __shared__ __half smh[];
    const uint32_t sXb = s2u(smh);
    const uint32_t sWb = sXb + 3 * 4608 * 2;
    const int tid = threadIdx.x, wp = tid >> 5, lane = tid & 31;
    const int r = lane >> 2, q = lane & 3;
    const int wm = wp >> 2, wn = wp & 3;
    const int hw0 = blockIdx.x * 64, o0 = blockIdx.y * 128, b = blockIdx.z;
    const uint32_t aof = a_off16(lane, STRB), bof = b_off16(lane, STRB);

#define QKV_PF(K0, BUF) {                                                       \
    _Pragma("unroll") for (int rr = 0; rr < 2; rr++) {                          \
        int f = tid + rr * 256, row = f >> 3, ch = (f & 7) * 8;                 \
        cpa16(sXb + (uint32_t)((BUF) * 4608 + row * 72 + ch) * 2u,              \
              g_xt + ((b * HW) + hw0 + row) * CIN + (K0) + ch);                 \
    }                                                                           \
    _Pragma("unroll") for (int rr = 0; rr < 4; rr++) {                          \
        int f = tid + rr * 256, row = f >> 3, ch = (f & 7) * 8;                 \
        cpa16(sWb + (uint32_t)((BUF) * 9216 + row * 72 + ch) * 2u,              \
              g_wq + (o0 + row) * CIN + (K0) + ch);                             \
    }                                                                           \
    cpcommit(); }

    QKV_PF(0, 0);
    QKV_PF(64, 1);
    float acc[2][4][4] = {};

    for (int kk = 0; kk < 8; kk++) {
        const int buf = kk % 3;
        CPWAIT(1);
        __syncthreads();
        if (kk + 2 < 8) QKV_PF((kk + 2) * 64, (kk + 2) % 3);

        const uint32_t xa = sXb + (uint32_t)(buf * 4608 + wm * 32 * 72) * 2u + aof;
        const uint32_t wa = sWb + (uint32_t)(buf * 9216 + wn * 32 * 72) * 2u + bof;
#pragma unroll
        for (int s = 0; s < 4; s++) {
            uint32_t aX[2][4];
            ldsm4(aX[0], xa + s * 32);
            ldsm4(aX[1], xa + 16 * STRB + s * 32);
#pragma unroll
            for (int j2 = 0; j2 < 2; j2++) {
                uint32_t bb[4]; ldsm4(bb, wa + j2 * 16 * STRB + s * 32);
#pragma unroll
                for (int mi = 0; mi < 2; mi++) {
                    mma16(acc[mi][j2 * 2],     aX[mi], bb[0], bb[1]);
                    mma16(acc[mi][j2 * 2 + 1], aX[mi], bb[2], bb[3]);
                }
            }
        }
    }

    const int g2 = b >> 2, vv = b & 3;
#pragma unroll
    for (int mi = 0; mi < 2; mi++) {
        int hwr = hw0 + wm * 32 + mi * 16 + r;
        int n0t = vv * HW + hwr, n1t = n0t + 8;
#pragma unroll
        for (int nj = 0; nj < 4; nj++) {
            int o = o0 + wn * 32 + nj * 8 + 2 * q;
            int head = o / 192, rem = o - head * 192, which = rem >> 6, d = rem & 63;
            int pp = g2 * 8 + head;
            float c0 = acc[mi][nj][0], c1 = acc[mi][nj][1];
            float c2 = acc[mi][nj][2], c3 = acc[mi][nj][3];
            __half* dst = (which == 0) ? g_q : (which == 1) ? g_k : g_v;
            float sc = (which == 0) ? QSCALE : 1.0f;
            *(__half2*)&dst[(pp * NTOK + n0t) * HD + d] = __floats2half2_rn(c0 * sc, c1 * sc);
            *(__half2*)&dst[(pp * NTOK + n1t) * HD + d] = __floats2half2_rn(c2 * sc, c3 * sc);
        }
    }
}

// ---------------------------------------------------------------------------
// Kernel B: flash attention fp16 — BM=128, 4 warps x m32, BN=64, 3-stage ring,
// S fp16-acc, P register-resident, FMA-pipe row sums, V [n][d] + trans LDSM.
// grid (18, 16), 128 thr, 2 CTAs/SM.
// ---------------------------------------------------------------------------
__global__ __launch_bounds__(128, 2) void flash_mma() {
    extern __shared__ __half smh[];
    const uint32_t sQb = s2u(smh);
    const uint32_t sKb = sQb + 128 * 72 * 2;
    const uint32_t sVb = sKb + 3 * 4608 * 2;

    const int tid = threadIdx.x, wm = tid >> 5, lane = tid & 31;
    const int r = lane >> 2, q = lane & 3;
    const int p = blockIdx.y, m0 = blockIdx.x * 128;

    const __half* Qb = g_q + (p * NTOK + m0) * HD;
    const __half* Kb = g_k + p * NTOK * HD;
    const __half* Vb = g_v + p * NTOK * HD;

    const uint32_t aof = a_off16(lane, STRB);
    const uint32_t bof = b_off16(lane, STRB);
    const uint32_t btf = bt_off16(lane, STRB);

#define FL_PF(N0, BUF) {                                                        \
    _Pragma("unroll") for (int rr = 0; rr < 4; rr++) {                          \
        int f = tid + rr * 128, row = f >> 3, ch = (f & 7) * 8;                 \
        cpa16(sKb + (uint32_t)((BUF) * 4608 + row * 72 + ch) * 2u,              \
              Kb + ((N0) + row) * HD + ch);                                     \
        cpa16(sVb + (uint32_t)((BUF) * 4608 + row * 72 + ch) * 2u,              \
              Vb + ((N0) + row) * HD + ch);                                     \
    }                                                                           \
    cpcommit(); }

    // stage Q (128 rows x 64 halves), then first two K/V stages
#pragma unroll
    for (int rr = 0; rr < 8; rr++) {
        int f = tid + rr * 128, row = f >> 3, ch = (f & 7) * 8;
        cpa16(sQb + (uint32_t)(row * 72 + ch) * 2u, Qb + row * HD + ch);
    }
    cpcommit();
    FL_PF(0, 0);
    FL_PF(64, 1);

    CPWAIT(1);            // Q + stage0 ready
    __syncthreads();
    uint32_t qf[2][4][4];
#pragma unroll
    for (int st = 0; st < 2; st++) {
        const uint32_t qa = sQb + (uint32_t)((wm * 32 + st * 16) * 72) * 2u + aof;
#pragma unroll
        for (int s = 0; s < 4; s++) ldsm4(qf[st][s], qa + s * 32);
    }

    float rO[2][8][4] = {};     // [strip][d-tile][4]
    float sr[2]  = {0.f, 0.f};  // per-thread partial row sums (row r)
    float sr8[2] = {0.f, 0.f};  // (row r+8)

    for (int it = 0; it < 36; it++) {
        const int buf = it % 3;
        if (it) { CPWAIT(1); __syncthreads(); }
        if (it + 2 < 36) FL_PF((it + 2) * 64, (it + 2) % 3);

        const uint32_t ka = sKb + (uint32_t)(buf * 4608) * 2u + bof;
        const uint32_t va = sVb + (uint32_t)(buf * 4608) * 2u + btf;

#pragma unroll
        for (int h = 0; h < 2; h++) {     // n in two 32-halves (sequential)
            // S(m32 x n32) = Q K^T, fp16 accumulate.
            uint32_t Sh[2][4][2] = {};
#pragma unroll
            for (int s = 0; s < 4; s++)
#pragma unroll
                for (int jn = 0; jn < 2; jn++) {
                    uint32_t bb[4];
                    ldsm4(bb, ka + (uint32_t)((h * 32 + jn * 16) * STRB) + s * 32);
#pragma unroll
                    for (int st = 0; st < 2; st++) {
                        mma16h(Sh[st][jn * 2],     qf[st][s], bb[0], bb[1]);
                        mma16h(Sh[st][jn * 2 + 1], qf[st][s], bb[2], bb[3]);
                    }
                }

            // p = exp2(S) directly on fp16 mma outputs; row sums on FMA pipe
            uint32_t pf[2][2][4];
#pragma unroll
            for (int st = 0; st < 2; st++) {
#pragma unroll
                for (int t = 0; t < 2; t++) {
                    __half2 e0 = h2exp2(*(__half2*)&Sh[st][2 * t][0]);
                    __half2 e1 = h2exp2(*(__half2*)&Sh[st][2 * t][1]);
                    __half2 e2 = h2exp2(*(__half2*)&Sh[st][2 * t + 1][0]);
                    __half2 e3 = h2exp2(*(__half2*)&Sh[st][2 * t + 1][1]);
                    pf[st][t][0] = *(uint32_t*)&e0;
                    pf[st][t][1] = *(uint32_t*)&e1;
                    pf[st][t][2] = *(uint32_t*)&e2;
                    pf[st][t][3] = *(uint32_t*)&e3;
                }
                __half2 a0 = __hadd2(H2(pf[st][0][0]), H2(pf[st][1][0]));
                __half2 a1 = __hadd2(H2(pf[st][0][2]), H2(pf[st][1][2]));
                __half2 b0 = __hadd2(H2(pf[st][0][1]), H2(pf[st][1][1]));
                __half2 b1 = __hadd2(H2(pf[st][0][3]), H2(pf[st][1][3]));
                float2 fa0 = __half22float2(a0), fa1 = __half22float2(a1);
                float2 fb0 = __half22float2(b0), fb1 = __half22float2(b1);
                sr[st]  += (fa0.x + fa0.y) + (fa1.x + fa1.y);
                sr8[st] += (fb0.x + fb0.y) + (fb1.x + fb1.y);
            }

            // O(m32 x d64) += P @ V  (V tile [n][d], trans LDSM)
#pragma unroll
            for (int t = 0; t < 2; t++)
#pragma unroll
                for (int j = 0; j < 4; j++) {
                    uint32_t bb[4];
                    ldsm4t(bb, va + (uint32_t)((h * 32 + t * 16) * STRB) + j * 32);
#pragma unroll
                    for (int st = 0; st < 2; st++) {
                        mma16(rO[st][2 * j],     pf[st][t], bb[0], bb[1]);
                        mma16(rO[st][2 * j + 1], pf[st][t], bb[2], bb[3]);
                    }
                }
        }
    }

    // epilogue: quad shuffle-reduce of row sums, normalize, write g_ao
    const int head = p & 7, gi = p >> 3;
#pragma unroll
    for (int st = 0; st < 2; st++) {
        float l0 = sr[st], l1 = sr8[st];
        l0 += __shfl_xor_sync(0xffffffffu, l0, 1);
        l0 += __shfl_xor_sync(0xffffffffu, l0, 2);
        l1 += __shfl_xor_sync(0xffffffffu, l1, 1);
        l1 += __shfl_xor_sync(0xffffffffu, l1, 2);
        const float i0 = 1.f / l0, i1 = 1.f / l1;
        const int row0 = m0 + wm * 32 + st * 16 + r, row1 = row0 + 8;
        const int v0 = row0 / HW, v1 = row1 / HW;
        __half* o0p = g_ao + ((gi * 4 + v0) * HW + (row0 - v0 * HW)) * CIN + head * 64;
        __half* o1p = g_ao + ((gi * 4 + v1) * HW + (row1 - v1 * HW)) * CIN + head * 64;
#pragma unroll
        for (int dt = 0; dt < 8; dt++) {
            *(__half2*)&o0p[dt * 8 + 2 * q] =
                __floats2half2_rn(rO[st][dt][0] * i0, rO[st][dt][1] * i0);
            *(__half2*)&o1p[dt * 8 + 2 * q] =
                __floats2half2_rn(rO[st][dt][2] * i1, rO[st][dt][3] * i1);
        }
    }
}

// ---------------------------------------------------------------------------
// Kernel C: proj + bias. D[m=o 128][n=hw 64] = W[o][c] @ AO[hw][c]^T.
// 3-stage cp.async pipeline. smem 82944 B, 2 CTAs/SM.
// ---------------------------------------------------------------------------
__global__ __launch_bounds__(256, 2) void proj_mma(const float* __restrict__ bias,
                                                   float* __restrict__ out) {
    extern __shared__ __half smh[];
    const uint32_t sWb = s2u(smh);
    const uint32_t sBb = sWb + 3 * 9216 * 2;
    const int tid = threadIdx.x, wp = tid >> 5, lane = tid & 31;
    const int r = lane >> 2, q = lane & 3;
    const int wm = wp >> 1, wn = wp & 1;
    const int o0 = blockIdx.x * 128, hw0 = blockIdx.y * 64, b = blockIdx.z;
    const uint32_t aof = a_off16(lane, STRB), bof = b_off16(lane, STRB);

#define PRJ_PF(K0, BUF) {                                                       \
    _Pragma("unroll") for (int rr = 0; rr < 4; rr++) {                          \
        int f = tid + rr * 256, row = f >> 3, ch = (f & 7) * 8;                 \
        cpa16(sWb + (uint32_t)((BUF) * 9216 + row * 72 + ch) * 2u,              \
              g_wp + (o0 + row) * CIN + (K0) + ch);                             \
    }                                                                           \
    _Pragma("unroll") for (int rr = 0; rr < 2; rr++) {                          \
        int f = tid + rr * 256, row = f >> 3, ch = (f & 7) * 8;                 \
        cpa16(sBb + (uint32_t)((BUF) * 4608 + row * 72 + ch) * 2u,              \
              g_ao + ((b * HW) + hw0 + row) * CIN + (K0) + ch);                 \
    }                                                                           \
    cpcommit(); }

    PRJ_PF(0, 0);
    PRJ_PF(64, 1);
    float acc[2][4][4] = {};

    for (int kk = 0; kk < 8; kk++) {
        const int buf = kk % 3;
        CPWAIT(1);
        __syncthreads();
        if (kk + 2 < 8) PRJ_PF((kk + 2) * 64, (kk + 2) % 3);

        const uint32_t wa = sWb + (uint32_t)(buf * 9216 + wm * 32 * 72) * 2u + aof;
        const uint32_t xa = sBb + (uint32_t)(buf * 4608 + wn * 32 * 72) * 2u + bof;
#pragma unroll
        for (int s = 0; s < 4; s++) {
            uint32_t aW[2][4];
            ldsm4(aW[0], wa + s * 32);
            ldsm4(aW[1], wa + 16 * STRB + s * 32);
#pragma unroll
            for (int j2 = 0; j2 < 2; j2++) {
                uint32_t bb[4]; ldsm4(bb, xa + j2 * 16 * STRB + s * 32);
#pragma unroll
                for (int mi = 0; mi < 2; mi++) {
                    mma16(acc[mi][j2 * 2],     aW[mi], bb[0], bb[1]);
                    mma16(acc[mi][j2 * 2 + 1], aW[mi], bb[2], bb[3]);
                }
            }
        }
    }

#pragma unroll
    for (int mi = 0; mi < 2; mi++) {
        int o_r = o0 + wm * 32 + mi * 16 + r;
        float bv0 = bias[o_r], bv1 = bias[o_r + 8];
#pragma unroll
        for (int nj = 0; nj < 4; nj++) {
            int hw = hw0 + wn * 32 + nj * 8 + 2 * q;
            *(float2*)&out[(b * CIN + o_r) * HW + hw] =
                make_float2(acc[mi][nj][0] + bv0, acc[mi][nj][1] + bv0);
            *(float2*)&out[(b * CIN + o_r + 8) * HW + hw] =
                make_float2(acc[mi][nj][2] + bv1, acc[mi][nj][3] + bv1);
        }
    }
}

// ---------------------------------------------------------------------------
extern "C" void kernel_launch(void* const* d_in, const int* in_sizes, int n_in,
                              void* d_out, int out_size) {
    const float* x      = (const float*)d_in[0];
    const float* w_qkv  = (const float*)d_in[1];
    const float* w_proj = (const float*)d_in[2];
    const float* b_proj = (const float*)d_in[3];
    float* out = (float*)d_out;

    cudaFuncSetAttribute(qkv_mma,   cudaFuncAttributeMaxDynamicSharedMemorySize, 82944);
    cudaFuncSetAttribute(flash_mma, cudaFuncAttributeMaxDynamicSharedMemorySize, 73728);
    cudaFuncSetAttribute(proj_mma,  cudaFuncAttributeMaxDynamicSharedMemorySize, 82944);

    prep<<<1600, 256>>>((const float4*)w_qkv, (const float4*)w_proj, x);
    qkv_mma<<<dim3(9, 12, 8), 256, 82944>>>();
    flash_mma<<<dim3(18, 16), 128, 73728>>>();
    proj_mma<<<dim3(4, 9, 8), 256, 82944>>>(b_proj, out);
}

// round 17
// speedup vs baseline: 1.6114x; 1.0022x over previous
#include <cuda_runtime.h>
#include <cuda_fp16.h>
#include <cstdint>

#define HW     576
#define CIN    512
#define HD     64
#define NTOK   2304      // V_NUM * HW
#define NPAIR  16        // groups(2) * heads(8)
#define NB     8
#define QSCALE (0.125f * 1.4426950408889634f)   // hd^-0.5 * log2(e)

// Scratch (device globals: allocation-free rule). All fp16.
__device__ __align__(16) __half g_xt[NB * HW * CIN];     // x transposed [b][hw][c]
__device__ __align__(16) __half g_wq[3 * CIN * CIN];     // w_qkv [o][c]
__device__ __align__(16) __half g_wp[CIN * CIN];         // w_proj [o][c]
__device__ __align__(16) __half g_q[NPAIR * NTOK * HD];  // [p][n][d], scale folded
__device__ __align__(16) __half g_k[NPAIR * NTOK * HD];  // [p][n][d]
__device__ __align__(16) __half g_v[NPAIR * NTOK * HD];  // [p][n][d]
__device__ __align__(16) __half g_ao[NB * HW * CIN];     // attn out [b][hw][c]

// ---------------- helpers ----------------
__device__ __forceinline__ void mma16(float* c, const uint32_t* a, uint32_t b0, uint32_t b1) {
    asm("mma.sync.aligned.m16n8k16.row.col.f32.f16.f16.f32 "
        "{%0,%1,%2,%3}, {%4,%5,%6,%7}, {%8,%9}, {%0,%1,%2,%3};\n"
        : "+f"(c[0]), "+f"(c[1]), "+f"(c[2]), "+f"(c[3])
        : "r"(a[0]), "r"(a[1]), "r"(a[2]), "r"(a[3]), "r"(b0), "r"(b1));
}
// fp16 accumulate variant: D/C are 2 x .f16x2 regs (half2 row r, half2 row r+8)
__device__ __forceinline__ void mma16h(uint32_t* c, const uint32_t* a, uint32_t b0, uint32_t b1) {
    asm("mma.sync.aligned.m16n8k16.row.col.f16.f16.f16.f16 "
        "{%0,%1}, {%2,%3,%4,%5}, {%6,%7}, {%0,%1};\n"
        : "+r"(c[0]), "+r"(c[1])
        : "r"(a[0]), "r"(a[1]), "r"(a[2]), "r"(a[3]), "r"(b0), "r"(b1));
}
__device__ __forceinline__ void ldsm4(uint32_t* d, uint32_t a) {
    asm volatile("ldmatrix.sync.aligned.m8n8.x4.shared.b16 {%0,%1,%2,%3}, [%4];\n"
        : "=r"(d[0]), "=r"(d[1]), "=r"(d[2]), "=r"(d[3]) : "r"(a));
}
__device__ __forceinline__ void ldsm4t(uint32_t* d, uint32_t a) {
    asm volatile("ldmatrix.sync.aligned.m8n8.x4.trans.shared.b16 {%0,%1,%2,%3}, [%4];\n"
        : "=r"(d[0]), "=r"(d[1]), "=r"(d[2]), "=r"(d[3]) : "r"(a));
}
__device__ __forceinline__ uint32_t s2u(const void* p) {
    return (uint32_t)__cvta_generic_to_shared(p);
}
__device__ __forceinline__ void cpa16(uint32_t dst, const void* src) {
    asm volatile("cp.async.cg.shared.global [%0], [%1], 16;\n" :: "r"(dst), "l"(src));
}
__device__ __forceinline__ void cpcommit() {
    asm volatile("cp.async.commit_group;\n" ::: "memory");
}
#define CPWAIT(n) asm volatile("cp.async.wait_group %0;\n" :: "n"(n) : "memory")

// fp16 LDSM lane offsets (bytes). strideB = row stride in bytes.
__device__ __forceinline__ uint32_t a_off16(int lane, int strideB) {
    return (uint32_t)(((lane & 7) + ((lane >> 3) & 1) * 8) * strideB + (lane >> 4) * 16);
}
__device__ __forceinline__ uint32_t b_off16(int lane, int strideB) {
    return (uint32_t)(((lane & 7) + ((lane >> 4) & 1) * 8) * strideB + ((lane >> 3) & 1) * 16);
}
// trans B-frag offsets (V tile stored [n][d]); swap bits 3/4 vs b_off16.
__device__ __forceinline__ uint32_t bt_off16(int lane, int strideB) {
    return (uint32_t)(((lane & 7) + ((lane >> 3) & 1) * 8) * strideB + ((lane >> 4) & 1) * 16);
}

#define STRB 144      // 72 halves per smem row
#define H2(u) (*(__half2*)&(u))

// ---------------------------------------------------------------------------
// Fused prologue: blocks [0,1024) convert weights; blocks [1024,1600)
// transpose+convert x [b][c][hw] -> g_xt [b][hw][c] fp16 (64x64 tiles).
// ---------------------------------------------------------------------------
__global__ __launch_bounds__(256) void prep(const float4* __restrict__ wq,
                                            const float4* __restrict__ wp,
                                            const float* __restrict__ x) {
    __shared__ float sT[64 * 65];
    const int tid = threadIdx.x;
    if (blockIdx.x < 1024) {
        int i = blockIdx.x * 256 + tid;
        float4 v; __half* dst;
        if (i < 196608) { v = wq[i];          dst = g_wq + i * 4; }
        else            { v = wp[i - 196608]; dst = g_wp + (i - 196608) * 4; }
        *(__half2*)dst       = __floats2half2_rn(v.x, v.y);
        *(__half2*)(dst + 2) = __floats2half2_rn(v.z, v.w);
        return;
    }
    const int bid = blockIdx.x - 1024;               // 576 tiles: 9 x 8 x 8
    const int hw0 = (bid % 9) * 64;
    const int c0  = ((bid / 9) & 7) * 64;
    const int b   = bid / 72;
#pragma unroll
    for (int rr = 0; rr < 4; rr++) {
        int f = tid + rr * 256, row = f >> 4, h4 = (f & 15) * 4;
        float4 v = *(const float4*)&x[((b * CIN) + c0 + row) * HW + hw0 + h4];
        sT[row * 65 + h4 + 0] = v.x; sT[row * 65 + h4 + 1] = v.y;
        sT[row * 65 + h4 + 2] = v.z; sT[row * 65 + h4 + 3] = v.w;
    }
    __syncthreads();
    {
        int f = tid, hwr = f >> 2, cc = (f & 3) * 16;   // 256 items exactly
        __half* dst = g_xt + ((b * HW) + hw0 + hwr) * CIN + c0 + cc;
#pragma unroll
        for (int j = 0; j < 8; j++)
            *(__half2*)(dst + 2 * j) =
                __floats2half2_rn(sT[(cc + 2 * j) * 65 + hwr], sT[(cc + 2 * j + 1) * 65 + hwr]);
    }
}

// ---------------------------------------------------------------------------
// Kernel A: QKV, batch-pair blocked. For bp: b0=2bp, b1=2bp+1 share the W tile.
// D[m=hw 64][n=o 128] per batch, K=512, BK=64, 2-stage cp.async.
// smem: sX 2bufs x 2bs x [64][72]h (36864 B) | sW 2bufs x [128][72]h (36864 B).
// grid (9, 12, 4), 256 thr, 2 CTAs/SM.
// ---------------------------------------------------------------------------
__global__ __launch_bounds__(256, 2) void qkv_mma() {
    extern __shared__ __half smh[];
    const uint32_t sXb = s2u(smh);                // buf*9216h + bs*4608h
    const uint32_t sWb = sXb + 4 * 4608 * 2;      // buf*9216h
    const int tid = threadIdx.x, wp = tid >> 5, lane = tid & 31;
    const int r = lane >> 2, q = lane & 3;
    const int wm = wp >> 2, wn = wp & 3;
    const int hw0 = blockIdx.x * 64, o0 = blockIdx.y * 128;
    const int b0 = blockIdx.z * 2, b1 = b0 + 1;
    const uint32_t aof = a_off16(lane, STRB), bof = b_off16(lane, STRB);

#define QKV_PF(K0, BUF) {                                                       \
    _Pragma("unroll") for (int rr = 0; rr < 2; rr++) {                          \
        int f = tid + rr * 256, row = f >> 3, ch = (f & 7) * 8;                 \
        cpa16(sXb + (uint32_t)((BUF) * 9216 + row * 72 + ch) * 2u,              \
              g_xt + ((b0 * HW) + hw0 + row) * CIN + (K0) + ch);                \
        cpa16(sXb + (uint32_t)((BUF) * 9216 + 4608 + row * 72 + ch) * 2u,       \
              g_xt + ((b1 * HW) + hw0 + row) * CIN + (K0) + ch);                \
    }                                                                           \
    _Pragma("unroll") for (int rr = 0; rr < 4; rr++) {                          \
        int f = tid + rr * 256, row = f >> 3, ch = (f & 7) * 8;                 \
        cpa16(sWb + (uint32_t)((BUF) * 9216 + row * 72 + ch) * 2u,              \
              g_wq + (o0 + row) * CIN + (K0) + ch);                             \
    }                                                                           \
    cpcommit(); }

    QKV_PF(0, 0);
    float acc[2][2][4][4] = {};   // [bs][mi][nj][4]

    for (int kk = 0; kk < 8; kk++) {
        const int buf = kk & 1;
        CPWAIT(0);
        __syncthreads();
        if (kk + 1 < 8) QKV_PF((kk + 1) * 64, buf ^ 1);

        const uint32_t xa = sXb + (uint32_t)(buf * 9216 + wm * 32 * 72) * 2u + aof;
        const uint32_t wa = sWb + (uint32_t)(buf * 9216 + wn * 32 * 72) * 2u + bof;
#pragma unroll
        for (int s = 0; s < 4; s++) {
            uint32_t aX[2][2][4];   // [bs][mi]
#pragma unroll
            for (int bs = 0; bs < 2; bs++) {
                ldsm4(aX[bs][0], xa + (uint32_t)(bs * 4608) * 2u + s * 32);
                ldsm4(aX[bs][1], xa + (uint32_t)(bs * 4608) * 2u + 16 * STRB + s * 32);
            }
#pragma unroll
            for (int j2 = 0; j2 < 2; j2++) {
                uint32_t bb[4]; ldsm4(bb, wa + j2 * 16 * STRB + s * 32);
#pragma unroll
                for (int bs = 0; bs < 2; bs++)
#pragma unroll
                    for (int mi = 0; mi < 2; mi++) {
                        mma16(acc[bs][mi][j2 * 2],     aX[bs][mi], bb[0], bb[1]);
                        mma16(acc[bs][mi][j2 * 2 + 1], aX[bs][mi], bb[2], bb[3]);
                    }
            }
        }
    }

#pragma unroll
    for (int bs = 0; bs < 2; bs++) {
        const int b = b0 + bs;
        const int g2 = b >> 2, vv = b & 3;
#pragma unroll
        for (int mi = 0; mi < 2; mi++) {
            int hwr = hw0 + wm * 32 + mi * 16 + r;
            int n0t = vv * HW + hwr, n1t = n0t + 8;
#pragma unroll
            for (int nj = 0; nj < 4; nj++) {
                int o = o0 + wn * 32 + nj * 8 + 2 * q;
                int head = o / 192, rem = o - head * 192, which = rem >> 6, d = rem & 63;
                int pp = g2 * 8 + head;
                float c0 = acc[bs][mi][nj][0], c1 = acc[bs][mi][nj][1];
                float c2 = acc[bs][mi][nj][2], c3 = acc[bs][mi][nj][3];
                __half* dst = (which == 0) ? g_q : (which == 1) ? g_k : g_v;
                float sc = (which == 0) ? QSCALE : 1.0f;
                *(__half2*)&dst[(pp * NTOK + n0t) * HD + d] = __floats2half2_rn(c0 * sc, c1 * sc);
                *(__half2*)&dst[(pp * NTOK + n1t) * HD + d] = __floats2half2_rn(c2 * sc, c3 * sc);
            }
        }
    }
}

// ---------------------------------------------------------------------------
// Kernel B: flash attention fp16 — BM=128, 4 warps x m32, BN=64, 3-stage ring,
// S fp16-acc, P register-resident, FMA-pipe row sums, V [n][d] + trans LDSM.
// grid (18, 16), 128 thr, 2 CTAs/SM.   (unchanged from 101.1 us winner)
// ---------------------------------------------------------------------------
__global__ __launch_bounds__(128, 2) void flash_mma() {
    extern __shared__ __half smh[];
    const uint32_t sQb = s2u(smh);
    const uint32_t sKb = sQb + 128 * 72 * 2;
    const uint32_t sVb = sKb + 3 * 4608 * 2;

    const int tid = threadIdx.x, wm = tid >> 5, lane = tid & 31;
    const int r = lane >> 2, q = lane & 3;
    const int p = blockIdx.y, m0 = blockIdx.x * 128;

    const __half* Qb = g_q + (p * NTOK + m0) * HD;
    const __half* Kb = g_k + p * NTOK * HD;
    const __half* Vb = g_v + p * NTOK * HD;

    const uint32_t aof = a_off16(lane, STRB);
    const uint32_t bof = b_off16(lane, STRB);
    const uint32_t btf = bt_off16(lane, STRB);

#define FL_PF(N0, BUF) {                                                        \
    _Pragma("unroll") for (int rr = 0; rr < 4; rr++) {                          \
        int f = tid + rr * 128, row = f >> 3, ch = (f & 7) * 8;                 \
        cpa16(sKb + (uint32_t)((BUF) * 4608 + row * 72 + ch) * 2u,              \
              Kb + ((N0) + row) * HD + ch);                                     \
        cpa16(sVb + (uint32_t)((BUF) * 4608 + row * 72 + ch) * 2u,              \
              Vb + ((N0) + row) * HD + ch);                                     \
    }                                                                           \
    cpcommit(); }

    // stage Q (128 rows x 64 halves), then first two K/V stages
#pragma unroll
    for (int rr = 0; rr < 8; rr++) {
        int f = tid + rr * 128, row = f >> 3, ch = (f & 7) * 8;
        cpa16(sQb + (uint32_t)(row * 72 + ch) * 2u, Qb + row * HD + ch);
    }
    cpcommit();
    FL_PF(0, 0);
    FL_PF(64, 1);

    CPWAIT(1);            // Q + stage0 ready
    __syncthreads();
    uint32_t qf[2][4][4];
#pragma unroll
    for (int st = 0; st < 2; st++) {
        const uint32_t qa = sQb + (uint32_t)((wm * 32 + st * 16) * 72) * 2u + aof;
#pragma unroll
        for (int s = 0; s < 4; s++) ldsm4(qf[st][s], qa + s * 32);
    }

    float rO[2][8][4] = {};     // [strip][d-tile][4]
    float sr[2]  = {0.f, 0.f};  // per-thread partial row sums (row r)
    float sr8[2] = {0.f, 0.f};  // (row r+8)

    for (int it = 0; it < 36; it++) {
        const int buf = it % 3;
        if (it) { CPWAIT(1); __syncthreads(); }
        if (it + 2 < 36) FL_PF((it + 2) * 64, (it + 2) % 3);

        const uint32_t ka = sKb + (uint32_t)(buf * 4608) * 2u + bof;
        const uint32_t va = sVb + (uint32_t)(buf * 4608) * 2u + btf;

#pragma unroll
        for (int h = 0; h < 2; h++) {     // n in two 32-halves (sequential)
            // S(m32 x n32) = Q K^T, fp16 accumulate.
            uint32_t Sh[2][4][2] = {};
#pragma unroll
            for (int s = 0; s < 4; s++)
#pragma unroll
                for (int jn = 0; jn < 2; jn++) {
                    uint32_t bb[4];
                    ldsm4(bb, ka + (uint32_t)((h * 32 + jn * 16) * STRB) + s * 32);
#pragma unroll
                    for (int st = 0; st < 2; st++) {
                        mma16h(Sh[st][jn * 2],     qf[st][s], bb[0], bb[1]);
                        mma16h(Sh[st][jn * 2 + 1], qf[st][s], bb[2], bb[3]);
                    }
                }

            // p = exp2(S) directly on fp16 mma outputs; row sums on FMA pipe
            uint32_t pf[2][2][4];
#pragma unroll
            for (int st = 0; st < 2; st++) {
#pragma unroll
                for (int t = 0; t < 2; t++) {
                    __half2 e0 = h2exp2(*(__half2*)&Sh[st][2 * t][0]);
                    __half2 e1 = h2exp2(*(__half2*)&Sh[st][2 * t][1]);
                    __half2 e2 = h2exp2(*(__half2*)&Sh[st][2 * t + 1][0]);
                    __half2 e3 = h2exp2(*(__half2*)&Sh[st][2 * t + 1][1]);
                    pf[st][t][0] = *(uint32_t*)&e0;
                    pf[st][t][1] = *(uint32_t*)&e1;
                    pf[st][t][2] = *(uint32_t*)&e2;
                    pf[st][t][3] = *(uint32_t*)&e3;
                }
                __half2 a0 = __hadd2(H2(pf[st][0][0]), H2(pf[st][1][0]));
                __half2 a1 = __hadd2(H2(pf[st][0][2]), H2(pf[st][1][2]));
                __half2 b0 = __hadd2(H2(pf[st][0][1]), H2(pf[st][1][1]));
                __half2 b1 = __hadd2(H2(pf[st][0][3]), H2(pf[st][1][3]));
                float2 fa0 = __half22float2(a0), fa1 = __half22float2(a1);
                float2 fb0 = __half22float2(b0), fb1 = __half22float2(b1);
                sr[st]  += (fa0.x + fa0.y) + (fa1.x + fa1.y);
                sr8[st] += (fb0.x + fb0.y) + (fb1.x + fb1.y);
            }

            // O(m32 x d64) += P @ V  (V tile [n][d], trans LDSM)
#pragma unroll
            for (int t = 0; t < 2; t++)
#pragma unroll
                for (int j = 0; j < 4; j++) {
                    uint32_t bb[4];
                    ldsm4t(bb, va + (uint32_t)((h * 32 + t * 16) * STRB) + j * 32);
#pragma unroll
                    for (int st = 0; st < 2; st++) {
                        mma16(rO[st][2 * j],     pf[st][t], bb[0], bb[1]);
                        mma16(rO[st][2 * j + 1], pf[st][t], bb[2], bb[3]);
                    }
                }
        }
    }

    // epilogue: quad shuffle-reduce of row sums, normalize, write g_ao
    const int head = p & 7, gi = p >> 3;
#pragma unroll
    for (int st = 0; st < 2; st++) {
        float l0 = sr[st], l1 = sr8[st];
        l0 += __shfl_xor_sync(0xffffffffu, l0, 1);
        l0 += __shfl_xor_sync(0xffffffffu, l0, 2);
        l1 += __shfl_xor_sync(0xffffffffu, l1, 1);
        l1 += __shfl_xor_sync(0xffffffffu, l1, 2);
        const float i0 = 1.f / l0, i1 = 1.f / l1;
        const int row0 = m0 + wm * 32 + st * 16 + r, row1 = row0 + 8;
        const int v0 = row0 / HW, v1 = row1 / HW;
        __half* o0p = g_ao + ((gi * 4 + v0) * HW + (row0 - v0 * HW)) * CIN + head * 64;
        __half* o1p = g_ao + ((gi * 4 + v1) * HW + (row1 - v1 * HW)) * CIN + head * 64;
#pragma unroll
        for (int dt = 0; dt < 8; dt++) {
            *(__half2*)&o0p[dt * 8 + 2 * q] =
                __floats2half2_rn(rO[st][dt][0] * i0, rO[st][dt][1] * i0);
            *(__half2*)&o1p[dt * 8 + 2 * q] =
                __floats2half2_rn(rO[st][dt][2] * i1, rO[st][dt][3] * i1);
        }
    }
}

// ---------------------------------------------------------------------------
// Kernel C: proj + bias, batch-pair blocked (b0=2bp, b1=2bp+1 share W tile).
// D[m=o 128][n=hw 64] per batch. 2-stage cp.async.
// smem: sW 2x[128][72]h (36864 B) | sB 2bufs x 2bs x [64][72]h (36864 B).
// grid (4, 9, 4), 256 thr, 2 CTAs/SM.
// ---------------------------------------------------------------------------
__global__ __launch_bounds__(256, 2) void proj_mma(const float* __restrict__ bias,
                                                   float* __restrict__ out) {
    extern __shared__ __half smh[];
    const uint32_t sWb = s2u(smh);                // buf*9216h
    const uint32_t sBb = sWb + 2 * 9216 * 2;      // buf*9216h + bs*4608h
    const int tid = threadIdx.x, wp = tid >> 5, lane = tid & 31;
    const int r = lane >> 2, q = lane & 3;
    const int wm = wp >> 1, wn = wp & 1;
    const int o0 = blockIdx.x * 128, hw0 = blockIdx.y * 64;
    const int b0 = blockIdx.z * 2, b1 = b0 + 1;
    const uint32_t aof = a_off16(lane, STRB), bof = b_off16(lane, STRB);

#define PRJ_PF(K0, BUF) {                                                       \
    _Pragma("unroll") for (int rr = 0; rr < 4; rr++) {                          \
        int f = tid + rr * 256, row = f >> 3, ch = (f & 7) * 8;                 \
        cpa16(sWb + (uint32_t)((BUF) * 9216 + row * 72 + ch) * 2u,              \
              g_wp + (o0 + row) * CIN + (K0) + ch);                             \
    }                                                                           \
    _Pragma("unroll") for (int rr = 0; rr < 2; rr++) {                          \
        int f = tid + rr * 256, row = f >> 3, ch = (f & 7) * 8;                 \
        cpa16(sBb + (uint32_t)((BUF) * 9216 + row * 72 + ch) * 2u,              \
              g_ao + ((b0 * HW) + hw0 + row) * CIN + (K0) + ch);                \
        cpa16(sBb + (uint32_t)((BUF) * 9216 + 4608 + row * 72 + ch) * 2u,       \
              g_ao + ((b1 * HW) + hw0 + row) * CIN + (K0) + ch);                \
    }                                                                           \
    cpcommit(); }

    PRJ_PF(0, 0);
    float acc[2][2][4][4] = {};   // [bs][mi][nj][4]

    for (int kk = 0; kk < 8; kk++) {
        const int buf = kk & 1;
        CPWAIT(0);
        __syncthreads();
        if (kk + 1 < 8) PRJ_PF((kk + 1) * 64, buf ^ 1);

        const uint32_t wa = sWb + (uint32_t)(buf * 9216 + wm * 32 * 72) * 2u + aof;
        const uint32_t xa = sBb + (uint32_t)(buf * 9216 + wn * 32 * 72) * 2u + bof;
#pragma unroll
        for (int s = 0; s < 4; s++) {
            uint32_t aW[2][4];
            ldsm4(aW[0], wa + s * 32);
            ldsm4(aW[1], wa + 16 * STRB + s * 32);
#pragma unroll
            for (int j2 = 0; j2 < 2; j2++) {
#pragma unroll
                for (int bs = 0; bs < 2; bs++) {
                    uint32_t bb[4];
                    ldsm4(bb, xa + (uint32_t)(bs * 4608) * 2u + j2 * 16 * STRB + s * 32);
#pragma unroll
                    for (int mi = 0; mi < 2; mi++) {
                        mma16(acc[bs][mi][j2 * 2],     aW[mi], bb[0], bb[1]);
                        mma16(acc[bs][mi][j2 * 2 + 1], aW[mi], bb[2], bb[3]);
                    }
                }
            }
        }
    }

#pragma unroll
    for (int bs = 0; bs < 2; bs++) {
        const int b = b0 + bs;
#pragma unroll
        for (int mi = 0; mi < 2; mi++) {
            int o_r = o0 + wm * 32 + mi * 16 + r;
            float bv0 = bias[o_r], bv1 = bias[o_r + 8];
#pragma unroll
            for (int nj = 0; nj < 4; nj++) {
                int hw = hw0 + wn * 32 + nj * 8 + 2 * q;
                *(float2*)&out[(b * CIN + o_r) * HW + hw] =
                    make_float2(acc[bs][mi][nj][0] + bv0, acc[bs][mi][nj][1] + bv0);
                *(float2*)&out[(b * CIN + o_r + 8) * HW + hw] =
                    make_float2(acc[bs][mi][nj][2] + bv1, acc[bs][mi][nj][3] + bv1);
            }
        }
    }
}

// ---------------------------------------------------------------------------
extern "C" void kernel_launch(void* const* d_in, const int* in_sizes, int n_in,
                              void* d_out, int out_size) {
    const float* x      = (const float*)d_in[0];
    const float* w_qkv  = (const float*)d_in[1];
    const float* w_proj = (const float*)d_in[2];
    const float* b_proj = (const float*)d_in[3];
    float* out = (float*)d_out;

    cudaFuncSetAttribute(qkv_mma,   cudaFuncAttributeMaxDynamicSharedMemorySize, 73728);
    cudaFuncSetAttribute(flash_mma, cudaFuncAttributeMaxDynamicSharedMemorySize, 73728);
    cudaFuncSetAttribute(proj_mma,  cudaFuncAttributeMaxDynamicSharedMemorySize, 73728);

    prep<<<1600, 256>>>((const float4*)w_qkv, (const float4*)w_proj, x);
    qkv_mma<<<dim3(9, 12, 4), 256, 73728>>>();
    flash_mma<<<dim3(18, 16), 128, 73728>>>();
    proj_mma<<<dim3(4, 9, 4), 256, 73728>>>(b_proj, out);
}